// round 1
// baseline (speedup 1.0000x reference)
#include <cuda_runtime.h>
#include <math.h>

#define BATCH 16
#define CH    512
#define HW    4096
#define HID   32
#define KSEL  153
#define NHALF (BATCH*HW)          /* 65536 GEMM columns per half     */
#define OUT_HALF ((long)BATCH*CH*HW) /* 33554432 elems per output tensor */

/* ------------------------------------------------------------------ */
/* device-global scratch (no allocations allowed)                      */
/* ------------------------------------------------------------------ */
__device__ float g_W[CH*CH];        // softmax(cross_att), tf32-rounded
__device__ float g_mean_t[BATCH*CH];
__device__ float g_mean_c[BATCH*CH];
__device__ float g_att_t[BATCH*CH];
__device__ float g_att_c[BATCH*CH];
__device__ float g_mask [BATCH*CH];

__device__ __forceinline__ float tf32r(float x) {
    unsigned u;
    asm("cvt.rna.tf32.f32 %0, %1;" : "=r"(u) : "f"(x));
    return __uint_as_float(u);
}

/* ------------------------------------------------------------------ */
/* 1. spatial means of x_t and x_c                                     */
/* ------------------------------------------------------------------ */
__global__ void mean_kernel(const float* __restrict__ xt,
                            const float* __restrict__ xc) {
    int ch = blockIdx.x, b = blockIdx.y, which = blockIdx.z;
    const float* src = which ? xc : xt;
    const float4* p = (const float4*)(src + ((long)(b*CH + ch))*HW);
    float s = 0.f;
    for (int i = threadIdx.x; i < HW/4; i += 256) {
        float4 v = p[i];
        s += (v.x + v.y) + (v.z + v.w);
    }
    for (int o = 16; o; o >>= 1) s += __shfl_xor_sync(0xffffffffu, s, o);
    __shared__ float ws[8];
    if ((threadIdx.x & 31) == 0) ws[threadIdx.x >> 5] = s;
    __syncthreads();
    if (threadIdx.x == 0) {
        float t = 0.f;
        #pragma unroll
        for (int i = 0; i < 8; i++) t += ws[i];
        (which ? g_mean_c : g_mean_t)[b*CH + ch] = t * (1.f/HW);
    }
}

/* ------------------------------------------------------------------ */
/* 2. SE MLPs + sigmoid + top-k mask (one block per batch)             */
/* ------------------------------------------------------------------ */
__global__ void se_kernel(const float* __restrict__ w1_t, const float* __restrict__ b1_t,
                          const float* __restrict__ w2_t, const float* __restrict__ b2_t,
                          const float* __restrict__ w1_c, const float* __restrict__ b1_c,
                          const float* __restrict__ w2_c, const float* __restrict__ b2_c) {
    int b = blockIdx.x;
    int tid = threadIdx.x;           // 512 threads
    int warp = tid >> 5, lane = tid & 31;
    __shared__ float m[2][CH];
    __shared__ float h[2][HID];
    __shared__ float at[CH];

    m[0][tid] = g_mean_t[b*CH + tid];
    m[1][tid] = g_mean_c[b*CH + tid];
    __syncthreads();

    // 64 hidden dot-products (2 branches x 32), 4 per warp
    for (int q = warp; q < 64; q += 16) {
        int br = q >> 5, j = q & 31;
        const float* w1 = br ? w1_c : w1_t;
        float s = 0.f;
        for (int i = lane; i < CH; i += 32) s += m[br][i] * w1[i*HID + j];
        for (int o = 16; o; o >>= 1) s += __shfl_xor_sync(0xffffffffu, s, o);
        if (lane == 0) {
            const float* b1 = br ? b1_c : b1_t;
            h[br][j] = fmaxf(s + b1[j], 0.f);
        }
    }
    __syncthreads();

    {
        float s0 = b2_t[tid], s1 = b2_c[tid];
        #pragma unroll
        for (int j = 0; j < HID; j++) {
            s0 += h[0][j] * w2_t[j*CH + tid];
            s1 += h[1][j] * w2_c[j*CH + tid];
        }
        float a0 = 1.f/(1.f + expf(-s0));
        float a1 = 1.f/(1.f + expf(-s1));
        at[tid] = a0;
        g_att_t[b*CH + tid] = a0;
        g_att_c[b*CH + tid] = a1;
    }
    __syncthreads();

    {   // rank of this channel among row (ties broken by lower index, as in top_k)
        float v = at[tid];
        int rank = 0;
        for (int j = 0; j < CH; j++) {
            float u = at[j];
            rank += (u > v) || (u == v && j < tid);
        }
        g_mask[b*CH + tid] = (rank < KSEL) ? 1.f : 0.f;
    }
}

/* ------------------------------------------------------------------ */
/* 3. row-softmax of cross_att, stored tf32-rounded                    */
/* ------------------------------------------------------------------ */
__global__ void softmax_kernel(const float* __restrict__ ca) {
    int r = blockIdx.x, tid = threadIdx.x;   // 256 threads
    __shared__ float red[8];
    float v0 = ca[r*CH + tid];
    float v1 = ca[r*CH + 256 + tid];
    float mx = fmaxf(v0, v1);
    for (int o = 16; o; o >>= 1) mx = fmaxf(mx, __shfl_xor_sync(0xffffffffu, mx, o));
    if ((tid & 31) == 0) red[tid >> 5] = mx;
    __syncthreads();
    float m2 = red[0];
    #pragma unroll
    for (int i = 1; i < 8; i++) m2 = fmaxf(m2, red[i]);
    float e0 = expf(v0 - m2), e1 = expf(v1 - m2);
    float s = e0 + e1;
    for (int o = 16; o; o >>= 1) s += __shfl_xor_sync(0xffffffffu, s, o);
    __syncthreads();
    if ((tid & 31) == 0) red[tid >> 5] = s;
    __syncthreads();
    float tot = 0.f;
    #pragma unroll
    for (int i = 0; i < 8; i++) tot += red[i];
    float inv = 1.f / tot;
    g_W[r*CH + tid]       = tf32r(e0 * inv);
    g_W[r*CH + 256 + tid] = tf32r(e1 * inv);
}

/* ------------------------------------------------------------------ */
/* 4. fused GEMM  C = W @ [x_c | x_t]  + epilogues                     */
/*    tf32 mma.sync m16n8k8, 128x128x16 tiles, double-buffered smem    */
/* ------------------------------------------------------------------ */
#define ASTRIDE 20
#define BSTRIDE 136

__global__ __launch_bounds__(256, 2)
void gemm_fused(const float* __restrict__ xt,
                const float* __restrict__ xc,
                float* __restrict__ out) {
    __shared__ float As[2][128*ASTRIDE];
    __shared__ float Bs[2][16*BSTRIDE];

    const int tid  = threadIdx.x;
    const int lane = tid & 31, warp = tid >> 5;
    const int g = lane >> 2, tg = lane & 3;
    const int wm = (warp >> 2) * 64;     // warp row offset  (2 warps in M)
    const int wn = (warp & 3)  * 32;     // warp col offset  (4 warps in N)

    const int  bm   = blockIdx.y * 128;
    const long n0   = (long)blockIdx.x * 128;
    const int  half = (n0 >= NHALF);
    const long rem  = n0 - (long)half * NHALF;
    const int  bb   = (int)(rem >> 12);
    const int  p0   = (int)(rem & 4095);
    const float* bsrc = (half ? xt : xc) + ((long)bb*CH)*HW + p0;

    const int arow = tid >> 2, ac4 = (tid & 3) * 4;  // A-tile loader coords
    const int brow = tid >> 5, bj  = (tid & 31) * 4; // B-tile loader coords

    float4 Areg0, Areg1, Breg0, Breg1;

    auto ldAB = [&](int k0) {
        Areg0 = *(const float4*)(g_W + (long)(bm + arow)      * CH + k0 + ac4);
        Areg1 = *(const float4*)(g_W + (long)(bm + arow + 64) * CH + k0 + ac4);
        Breg0 = *(const float4*)(bsrc + (long)(k0 + brow)     * HW + bj);
        Breg1 = *(const float4*)(bsrc + (long)(k0 + brow + 8) * HW + bj);
    };
    auto stAB = [&](int buf) {
        *(float4*)&As[buf][arow*ASTRIDE      + ac4] = Areg0;
        *(float4*)&As[buf][(arow+64)*ASTRIDE + ac4] = Areg1;
        float4 v = Breg0;
        v.x = tf32r(v.x); v.y = tf32r(v.y); v.z = tf32r(v.z); v.w = tf32r(v.w);
        *(float4*)&Bs[buf][brow*BSTRIDE + bj] = v;
        v = Breg1;
        v.x = tf32r(v.x); v.y = tf32r(v.y); v.z = tf32r(v.z); v.w = tf32r(v.w);
        *(float4*)&Bs[buf][(brow+8)*BSTRIDE + bj] = v;
    };

    float acc[4][4][4];
    #pragma unroll
    for (int i = 0; i < 4; i++)
        #pragma unroll
        for (int j = 0; j < 4; j++)
            #pragma unroll
            for (int k = 0; k < 4; k++) acc[i][j][k] = 0.f;

    ldAB(0);
    stAB(0);
    __syncthreads();

    for (int kt = 0; kt < 32; kt++) {
        const int buf = kt & 1;
        if (kt < 31) ldAB((kt + 1) * 16);

        #pragma unroll
        for (int kk = 0; kk < 16; kk += 8) {
            unsigned bf[4][2];
            #pragma unroll
            for (int nt = 0; nt < 4; nt++) {
                int col = wn + nt*8 + g;
                bf[nt][0] = __float_as_uint(Bs[buf][(kk+tg  )*BSTRIDE + col]);
                bf[nt][1] = __float_as_uint(Bs[buf][(kk+tg+4)*BSTRIDE + col]);
            }
            #pragma unroll
            for (int mt = 0; mt < 4; mt++) {
                int row = wm + mt*16;
                unsigned a0 = __float_as_uint(As[buf][(row+g  )*ASTRIDE + kk+tg  ]);
                unsigned a1 = __float_as_uint(As[buf][(row+g+8)*ASTRIDE + kk+tg  ]);
                unsigned a2 = __float_as_uint(As[buf][(row+g  )*ASTRIDE + kk+tg+4]);
                unsigned a3 = __float_as_uint(As[buf][(row+g+8)*ASTRIDE + kk+tg+4]);
                #pragma unroll
                for (int nt = 0; nt < 4; nt++) {
                    asm volatile(
                        "mma.sync.aligned.m16n8k8.row.col.f32.tf32.tf32.f32 "
                        "{%0,%1,%2,%3}, {%4,%5,%6,%7}, {%8,%9}, {%0,%1,%2,%3};\n"
                        : "+f"(acc[mt][nt][0]), "+f"(acc[mt][nt][1]),
                          "+f"(acc[mt][nt][2]), "+f"(acc[mt][nt][3])
                        : "r"(a0), "r"(a1), "r"(a2), "r"(a3),
                          "r"(bf[nt][0]), "r"(bf[nt][1]));
                }
            }
        }
        if (kt < 31) stAB(buf ^ 1);
        __syncthreads();
    }

    /* ---------------- fused epilogue ---------------- */
    const float* attp = (half ? g_att_c : g_att_t) + bb*CH;
    const float* xo   = half ? xc : xt;
    float*       op   = out + (half ? OUT_HALF : 0);

    float attv[4][2], mkv[4][2];
    #pragma unroll
    for (int mt = 0; mt < 4; mt++)
        #pragma unroll
        for (int h2 = 0; h2 < 2; h2++) {
            int mrow = bm + wm + mt*16 + g + h2*8;
            attv[mt][h2] = attp[mrow];
            mkv[mt][h2]  = half ? 0.f : g_mask[bb*CH + mrow];
        }

    #pragma unroll
    for (int mt = 0; mt < 4; mt++) {
        #pragma unroll
        for (int h2 = 0; h2 < 2; h2++) {
            int  mrow = bm + wm + mt*16 + g + h2*8;
            long base = ((long)bb*CH + mrow)*HW + p0;
            #pragma unroll
            for (int nt = 0; nt < 4; nt++) {
                int  col = wn + nt*8 + 2*tg;
                long idx = base + col;
                float2 xv = *(const float2*)(xo + idx);
                float c0 = acc[mt][nt][h2*2 + 0];
                float c1 = acc[mt][nt][h2*2 + 1];
                float2 o;
                if (!half) {
                    float a = attv[mt][h2], mk = mkv[mt][h2];
                    o.x = xv.x * a + mk * c0;
                    o.y = xv.y * a + mk * c1;
                } else {
                    float a = attv[mt][h2];
                    o.x = a * (xv.x + c0);
                    o.y = a * (xv.y + c1);
                }
                *(float2*)(op + idx) = o;
            }
        }
    }
}

/* ------------------------------------------------------------------ */
/* launch                                                              */
/* ------------------------------------------------------------------ */
extern "C" void kernel_launch(void* const* d_in, const int* in_sizes, int n_in,
                              void* d_out, int out_size) {
    const float* x_t  = (const float*)d_in[0];
    const float* x_c  = (const float*)d_in[1];
    const float* w1_t = (const float*)d_in[2];
    const float* b1_t = (const float*)d_in[3];
    const float* w2_t = (const float*)d_in[4];
    const float* b2_t = (const float*)d_in[5];
    const float* w1_c = (const float*)d_in[6];
    const float* b1_c = (const float*)d_in[7];
    const float* w2_c = (const float*)d_in[8];
    const float* b2_c = (const float*)d_in[9];
    const float* ca   = (const float*)d_in[10];
    float* out = (float*)d_out;

    mean_kernel<<<dim3(CH, BATCH, 2), 256>>>(x_t, x_c);
    softmax_kernel<<<CH, 256>>>(ca);
    se_kernel<<<BATCH, 512>>>(w1_t, b1_t, w2_t, b2_t, w1_c, b1_c, w2_c, b2_c);
    gemm_fused<<<dim3(1024, 4), 256>>>(x_t, x_c, out);
}

// round 2
// speedup vs baseline: 1.1486x; 1.1486x over previous
#include <cuda_runtime.h>
#include <math.h>

#define BATCH 16
#define CH    512
#define HW    4096
#define HID   32
#define KSEL  153
#define NHALF (BATCH*HW)
#define OUT_HALF ((long)BATCH*CH*HW)

#define STAGES  4
#define ASTRIDE 20
#define BSTRIDE 136
#define A_ELE   (128*ASTRIDE)   /* 2560 floats per stage */
#define B_ELE   (16*BSTRIDE)    /* 2176 floats per stage */
#define SMEM_BYTES (STAGES*(A_ELE+B_ELE)*4)

/* ------------------------------------------------------------------ */
__device__ float g_W[CH*CH];
__device__ float g_mean_t[BATCH*CH];
__device__ float g_mean_c[BATCH*CH];
__device__ float g_att_t[BATCH*CH];
__device__ float g_att_c[BATCH*CH];
__device__ float g_mask [BATCH*CH];

__device__ __forceinline__ float tf32r(float x) {
    unsigned u;
    asm("cvt.rna.tf32.f32 %0, %1;" : "=r"(u) : "f"(x));
    return __uint_as_float(u);
}
__device__ __forceinline__ unsigned tf32u(float x) {
    unsigned u;
    asm("cvt.rna.tf32.f32 %0, %1;" : "=r"(u) : "f"(x));
    return u;
}

/* ------------------------------------------------------------------ */
/* 1. spatial means: one warp per (tensor,b,ch) row                    */
/* ------------------------------------------------------------------ */
__global__ void mean_kernel(const float* __restrict__ xt,
                            const float* __restrict__ xc) {
    int row  = blockIdx.x * 8 + (threadIdx.x >> 5);   // 0..16383
    int lane = threadIdx.x & 31;
    int which = row >> 13;                            // 0: t, 1: c
    int r = row & 8191;                               // b*CH+ch
    const float4* p = (const float4*)((which ? xc : xt) + (long)r * HW);
    float s = 0.f;
    #pragma unroll
    for (int i = 0; i < 32; i++) {
        float4 v = p[lane + 32*i];
        s += (v.x + v.y) + (v.z + v.w);
    }
    for (int o = 16; o; o >>= 1) s += __shfl_xor_sync(0xffffffffu, s, o);
    if (lane == 0) (which ? g_mean_c : g_mean_t)[r] = s * (1.f/HW);
}

/* ------------------------------------------------------------------ */
/* 2. SE MLPs + sigmoid + top-k mask                                   */
/* ------------------------------------------------------------------ */
__global__ void se_kernel(const float* __restrict__ w1_t, const float* __restrict__ b1_t,
                          const float* __restrict__ w2_t, const float* __restrict__ b2_t,
                          const float* __restrict__ w1_c, const float* __restrict__ b1_c,
                          const float* __restrict__ w2_c, const float* __restrict__ b2_c) {
    int b = blockIdx.x;
    int tid = threadIdx.x;           // 512
    int warp = tid >> 5, lane = tid & 31;
    __shared__ float m[2][CH];
    __shared__ float h[2][HID];
    __shared__ float at[CH];

    m[0][tid] = g_mean_t[b*CH + tid];
    m[1][tid] = g_mean_c[b*CH + tid];
    __syncthreads();

    for (int q = warp; q < 64; q += 16) {
        int br = q >> 5, j = q & 31;
        const float* w1 = br ? w1_c : w1_t;
        float s = 0.f;
        for (int i = lane; i < CH; i += 32) s += m[br][i] * w1[i*HID + j];
        for (int o = 16; o; o >>= 1) s += __shfl_xor_sync(0xffffffffu, s, o);
        if (lane == 0) {
            const float* b1 = br ? b1_c : b1_t;
            h[br][j] = fmaxf(s + b1[j], 0.f);
        }
    }
    __syncthreads();

    {
        float s0 = b2_t[tid], s1 = b2_c[tid];
        #pragma unroll
        for (int j = 0; j < HID; j++) {
            s0 += h[0][j] * w2_t[j*CH + tid];
            s1 += h[1][j] * w2_c[j*CH + tid];
        }
        float a0 = 1.f/(1.f + expf(-s0));
        float a1 = 1.f/(1.f + expf(-s1));
        at[tid] = a0;
        g_att_t[b*CH + tid] = a0;
        g_att_c[b*CH + tid] = a1;
    }
    __syncthreads();

    {
        float v = at[tid];
        int rank = 0;
        for (int j = 0; j < CH; j++) {
            float u = at[j];
            rank += (u > v) || (u == v && j < tid);
        }
        g_mask[b*CH + tid] = (rank < KSEL) ? 1.f : 0.f;
    }
}

/* ------------------------------------------------------------------ */
/* 3. row-softmax of cross_att, tf32-rounded                           */
/* ------------------------------------------------------------------ */
__global__ void softmax_kernel(const float* __restrict__ ca) {
    int r = blockIdx.x, tid = threadIdx.x;   // 256
    __shared__ float red[8];
    float v0 = ca[r*CH + tid];
    float v1 = ca[r*CH + 256 + tid];
    float mx = fmaxf(v0, v1);
    for (int o = 16; o; o >>= 1) mx = fmaxf(mx, __shfl_xor_sync(0xffffffffu, mx, o));
    if ((tid & 31) == 0) red[tid >> 5] = mx;
    __syncthreads();
    float m2 = red[0];
    #pragma unroll
    for (int i = 1; i < 8; i++) m2 = fmaxf(m2, red[i]);
    float e0 = expf(v0 - m2), e1 = expf(v1 - m2);
    float s = e0 + e1;
    for (int o = 16; o; o >>= 1) s += __shfl_xor_sync(0xffffffffu, s, o);
    __syncthreads();
    if ((tid & 31) == 0) red[tid >> 5] = s;
    __syncthreads();
    float tot = 0.f;
    #pragma unroll
    for (int i = 0; i < 8; i++) tot += red[i];
    float inv = 1.f / tot;
    g_W[r*CH + tid]       = tf32r(e0 * inv);
    g_W[r*CH + 256 + tid] = tf32r(e1 * inv);
}

/* ------------------------------------------------------------------ */
/* 4. fused GEMM: 4-stage cp.async pipeline, L2-shared B panels        */
/* ------------------------------------------------------------------ */
__global__ __launch_bounds__(256, 2)
void gemm_fused(const float* __restrict__ xt,
                const float* __restrict__ xc,
                float* __restrict__ out) {
    extern __shared__ float smem[];
    float* Asm = smem;                    // STAGES * A_ELE
    float* Bsm = smem + STAGES*A_ELE;     // STAGES * B_ELE

    const int tid  = threadIdx.x;
    const int lane = tid & 31, warp = tid >> 5;
    const int g = lane >> 2, tg = lane & 3;
    const int wm = (warp >> 2) * 64;
    const int wn = (warp & 3)  * 32;

    /* adjacent CTAs share the same 128-column B panel (M-blocks 0..3) */
    const int  bid  = blockIdx.x;
    const int  bm   = (bid & 3) * 128;
    const long n0   = (long)(bid >> 2) * 128;
    const int  half = (n0 >= NHALF);
    const long rem  = n0 - (long)half * NHALF;
    const int  bb   = (int)(rem >> 12);
    const int  p0   = (int)(rem & 4095);
    const float* bsrc = (half ? xt : xc) + ((long)bb*CH)*HW + p0;

    const int arow = tid >> 2, ac4 = (tid & 3) * 4;
    const int brow = tid >> 5, bj  = (tid & 31) * 4;

    const float* aptr0 = g_W + (long)(bm + arow)      * CH + ac4;
    const float* aptr1 = g_W + (long)(bm + arow + 64) * CH + ac4;
    const float* bptr0 = bsrc + (long)brow     * HW + bj;
    const float* bptr1 = bsrc + (long)(brow+8) * HW + bj;

    unsigned sa0 = (unsigned)__cvta_generic_to_shared(Asm) + (arow*ASTRIDE + ac4)*4;
    unsigned sa1 = (unsigned)__cvta_generic_to_shared(Asm) + ((arow+64)*ASTRIDE + ac4)*4;
    unsigned sb0 = (unsigned)__cvta_generic_to_shared(Bsm) + (brow*BSTRIDE + bj)*4;
    unsigned sb1 = (unsigned)__cvta_generic_to_shared(Bsm) + ((brow+8)*BSTRIDE + bj)*4;

    auto issue = [&](int kt) {
        const int buf = kt % STAGES;
        const int k0  = kt * 16;
        unsigned ao = buf * (A_ELE*4), bo = buf * (B_ELE*4);
        asm volatile("cp.async.ca.shared.global [%0], [%1], 16;\n"
                     :: "r"(sa0 + ao), "l"(aptr0 + k0) : "memory");
        asm volatile("cp.async.ca.shared.global [%0], [%1], 16;\n"
                     :: "r"(sa1 + ao), "l"(aptr1 + k0) : "memory");
        asm volatile("cp.async.cg.shared.global [%0], [%1], 16;\n"
                     :: "r"(sb0 + bo), "l"(bptr0 + (long)k0*HW) : "memory");
        asm volatile("cp.async.cg.shared.global [%0], [%1], 16;\n"
                     :: "r"(sb1 + bo), "l"(bptr1 + (long)k0*HW) : "memory");
    };

    float acc[4][4][4];
    #pragma unroll
    for (int i = 0; i < 4; i++)
        #pragma unroll
        for (int j = 0; j < 4; j++)
            #pragma unroll
            for (int k = 0; k < 4; k++) acc[i][j][k] = 0.f;

    #pragma unroll
    for (int s = 0; s < STAGES-1; s++) {
        issue(s);
        asm volatile("cp.async.commit_group;\n" ::: "memory");
    }

    for (int kt = 0; kt < 32; kt++) {
        asm volatile("cp.async.wait_group %0;\n" :: "n"(STAGES-2) : "memory");
        __syncthreads();

        const int buf = kt % STAGES;
        const float* Asb = Asm + buf * A_ELE;
        const float* Bsb = Bsm + buf * B_ELE;

        #pragma unroll
        for (int kk = 0; kk < 16; kk += 8) {
            unsigned bf[4][2];
            #pragma unroll
            for (int nt = 0; nt < 4; nt++) {
                int col = wn + nt*8 + g;
                bf[nt][0] = tf32u(Bsb[(kk+tg  )*BSTRIDE + col]);
                bf[nt][1] = tf32u(Bsb[(kk+tg+4)*BSTRIDE + col]);
            }
            #pragma unroll
            for (int mt = 0; mt < 4; mt++) {
                int row = wm + mt*16;
                unsigned a0 = __float_as_uint(Asb[(row+g  )*ASTRIDE + kk+tg  ]);
                unsigned a1 = __float_as_uint(Asb[(row+g+8)*ASTRIDE + kk+tg  ]);
                unsigned a2 = __float_as_uint(Asb[(row+g  )*ASTRIDE + kk+tg+4]);
                unsigned a3 = __float_as_uint(Asb[(row+g+8)*ASTRIDE + kk+tg+4]);
                #pragma unroll
                for (int nt = 0; nt < 4; nt++) {
                    asm volatile(
                        "mma.sync.aligned.m16n8k8.row.col.f32.tf32.tf32.f32 "
                        "{%0,%1,%2,%3}, {%4,%5,%6,%7}, {%8,%9}, {%0,%1,%2,%3};\n"
                        : "+f"(acc[mt][nt][0]), "+f"(acc[mt][nt][1]),
                          "+f"(acc[mt][nt][2]), "+f"(acc[mt][nt][3])
                        : "r"(a0), "r"(a1), "r"(a2), "r"(a3),
                          "r"(bf[nt][0]), "r"(bf[nt][1]));
                }
            }
        }
        int nk = kt + STAGES - 1;
        if (nk < 32) issue(nk);
        asm volatile("cp.async.commit_group;\n" ::: "memory");
    }

    /* ---------------- fused epilogue ---------------- */
    const float* attp = (half ? g_att_c : g_att_t) + bb*CH;
    const float* xo   = half ? xc : xt;
    float*       op   = out + (half ? OUT_HALF : 0);

    float attv[4][2], mkv[4][2];
    #pragma unroll
    for (int mt = 0; mt < 4; mt++)
        #pragma unroll
        for (int h2 = 0; h2 < 2; h2++) {
            int mrow = bm + wm + mt*16 + g + h2*8;
            attv[mt][h2] = attp[mrow];
            mkv[mt][h2]  = half ? 0.f : g_mask[bb*CH + mrow];
        }

    #pragma unroll
    for (int mt = 0; mt < 4; mt++) {
        #pragma unroll
        for (int h2 = 0; h2 < 2; h2++) {
            int  mrow = bm + wm + mt*16 + g + h2*8;
            long base = ((long)bb*CH + mrow)*HW + p0;
            #pragma unroll
            for (int nt = 0; nt < 4; nt++) {
                int  col = wn + nt*8 + 2*tg;
                long idx = base + col;
                float2 xv = *(const float2*)(xo + idx);
                float c0 = acc[mt][nt][h2*2 + 0];
                float c1 = acc[mt][nt][h2*2 + 1];
                float2 o;
                if (!half) {
                    float a = attv[mt][h2], mk = mkv[mt][h2];
                    o.x = xv.x * a + mk * c0;
                    o.y = xv.y * a + mk * c1;
                } else {
                    float a = attv[mt][h2];
                    o.x = a * (xv.x + c0);
                    o.y = a * (xv.y + c1);
                }
                *(float2*)(op + idx) = o;
            }
        }
    }
}

/* ------------------------------------------------------------------ */
extern "C" void kernel_launch(void* const* d_in, const int* in_sizes, int n_in,
                              void* d_out, int out_size) {
    const float* x_t  = (const float*)d_in[0];
    const float* x_c  = (const float*)d_in[1];
    const float* w1_t = (const float*)d_in[2];
    const float* b1_t = (const float*)d_in[3];
    const float* w2_t = (const float*)d_in[4];
    const float* b2_t = (const float*)d_in[5];
    const float* w1_c = (const float*)d_in[6];
    const float* b1_c = (const float*)d_in[7];
    const float* w2_c = (const float*)d_in[8];
    const float* b2_c = (const float*)d_in[9];
    const float* ca   = (const float*)d_in[10];
    float* out = (float*)d_out;

    static int smem_set = 0;
    if (!smem_set) {
        cudaFuncSetAttribute(gemm_fused,
                             cudaFuncAttributeMaxDynamicSharedMemorySize,
                             SMEM_BYTES);
        smem_set = 1;
    }

    mean_kernel<<<2048, 256>>>(x_t, x_c);
    softmax_kernel<<<CH, 256>>>(ca);
    se_kernel<<<BATCH, 512>>>(w1_t, b1_t, w2_t, b2_t, w1_c, b1_c, w2_c, b2_c);
    gemm_fused<<<4096, 256, SMEM_BYTES>>>(x_t, x_c, out);
}

// round 3
// speedup vs baseline: 1.1503x; 1.0015x over previous
#include <cuda_runtime.h>
#include <math.h>

#define BATCH 16
#define CH    512
#define HW    4096
#define HID   32
#define KSEL  153
#define NHALF (BATCH*HW)
#define OUT_HALF ((long)BATCH*CH*HW)

#define STAGES  4
#define ASTRIDE 20
#define BSTRIDE 136
#define A_ELE   (128*ASTRIDE)   /* 2560 floats per stage */
#define B_ELE   (16*BSTRIDE)    /* 2176 floats per stage */
#define SMEM_BYTES (STAGES*(A_ELE+B_ELE)*4)

/* ------------------------------------------------------------------ */
__device__ float g_W[CH*CH];
__device__ float g_mean_t[BATCH*CH];
__device__ float g_mean_c[BATCH*CH];
__device__ float g_att_t[BATCH*CH];
__device__ float g_att_c[BATCH*CH];
__device__ float g_mask [BATCH*CH];

__device__ __forceinline__ float tf32r(float x) {
    unsigned u;
    asm("cvt.rna.tf32.f32 %0, %1;" : "=r"(u) : "f"(x));
    return __uint_as_float(u);
}
__device__ __forceinline__ unsigned tf32u(float x) {
    unsigned u;
    asm("cvt.rna.tf32.f32 %0, %1;" : "=r"(u) : "f"(x));
    return u;
}

/* ------------------------------------------------------------------ */
/* 1. spatial means: one warp per (tensor,b,ch) row                    */
/* ------------------------------------------------------------------ */
__global__ void mean_kernel(const float* __restrict__ xt,
                            const float* __restrict__ xc) {
    int row  = blockIdx.x * 8 + (threadIdx.x >> 5);   // 0..16383
    int lane = threadIdx.x & 31;
    int which = row >> 13;                            // 0: t, 1: c
    int r = row & 8191;                               // b*CH+ch
    const float4* p = (const float4*)((which ? xc : xt) + (long)r * HW);
    float s = 0.f;
    #pragma unroll
    for (int i = 0; i < 32; i++) {
        float4 v = p[lane + 32*i];
        s += (v.x + v.y) + (v.z + v.w);
    }
    for (int o = 16; o; o >>= 1) s += __shfl_xor_sync(0xffffffffu, s, o);
    if (lane == 0) (which ? g_mean_c : g_mean_t)[r] = s * (1.f/HW);
}

/* ------------------------------------------------------------------ */
/* 2. SE MLPs + sigmoid + top-k mask                                   */
/* ------------------------------------------------------------------ */
__global__ void se_kernel(const float* __restrict__ w1_t, const float* __restrict__ b1_t,
                          const float* __restrict__ w2_t, const float* __restrict__ b2_t,
                          const float* __restrict__ w1_c, const float* __restrict__ b1_c,
                          const float* __restrict__ w2_c, const float* __restrict__ b2_c) {
    int b = blockIdx.x;
    int tid = threadIdx.x;           // 512
    int warp = tid >> 5, lane = tid & 31;
    __shared__ float m[2][CH];
    __shared__ float h[2][HID];
    __shared__ float at[CH];

    m[0][tid] = g_mean_t[b*CH + tid];
    m[1][tid] = g_mean_c[b*CH + tid];
    __syncthreads();

    for (int q = warp; q < 64; q += 16) {
        int br = q >> 5, j = q & 31;
        const float* w1 = br ? w1_c : w1_t;
        float s = 0.f;
        for (int i = lane; i < CH; i += 32) s += m[br][i] * w1[i*HID + j];
        for (int o = 16; o; o >>= 1) s += __shfl_xor_sync(0xffffffffu, s, o);
        if (lane == 0) {
            const float* b1 = br ? b1_c : b1_t;
            h[br][j] = fmaxf(s + b1[j], 0.f);
        }
    }
    __syncthreads();

    {
        float s0 = b2_t[tid], s1 = b2_c[tid];
        #pragma unroll
        for (int j = 0; j < HID; j++) {
            s0 += h[0][j] * w2_t[j*CH + tid];
            s1 += h[1][j] * w2_c[j*CH + tid];
        }
        float a0 = 1.f/(1.f + expf(-s0));
        float a1 = 1.f/(1.f + expf(-s1));
        at[tid] = a0;
        g_att_t[b*CH + tid] = a0;
        g_att_c[b*CH + tid] = a1;
    }
    __syncthreads();

    {
        float v = at[tid];
        int rank = 0;
        for (int j = 0; j < CH; j++) {
            float u = at[j];
            rank += (u > v) || (u == v && j < tid);
        }
        g_mask[b*CH + tid] = (rank < KSEL) ? 1.f : 0.f;
    }
}

/* ------------------------------------------------------------------ */
/* 3. row-softmax of cross_att, tf32-rounded                           */
/* ------------------------------------------------------------------ */
__global__ void softmax_kernel(const float* __restrict__ ca) {
    int r = blockIdx.x, tid = threadIdx.x;   // 256
    __shared__ float red[8];
    float v0 = ca[r*CH + tid];
    float v1 = ca[r*CH + 256 + tid];
    float mx = fmaxf(v0, v1);
    for (int o = 16; o; o >>= 1) mx = fmaxf(mx, __shfl_xor_sync(0xffffffffu, mx, o));
    if ((tid & 31) == 0) red[tid >> 5] = mx;
    __syncthreads();
    float m2 = red[0];
    #pragma unroll
    for (int i = 1; i < 8; i++) m2 = fmaxf(m2, red[i]);
    float e0 = expf(v0 - m2), e1 = expf(v1 - m2);
    float s = e0 + e1;
    for (int o = 16; o; o >>= 1) s += __shfl_xor_sync(0xffffffffu, s, o);
    __syncthreads();
    if ((tid & 31) == 0) red[tid >> 5] = s;
    __syncthreads();
    float tot = 0.f;
    #pragma unroll
    for (int i = 0; i < 8; i++) tot += red[i];
    float inv = 1.f / tot;
    g_W[r*CH + tid]       = tf32r(e0 * inv);
    g_W[r*CH + 256 + tid] = tf32r(e1 * inv);
}

/* ------------------------------------------------------------------ */
/* 4. fused GEMM: 4-stage cp.async pipeline, L2-shared B panels        */
/* ------------------------------------------------------------------ */
__global__ __launch_bounds__(256, 2)
void gemm_fused(const float* __restrict__ xt,
                const float* __restrict__ xc,
                float* __restrict__ out) {
    extern __shared__ float smem[];
    float* Asm = smem;                    // STAGES * A_ELE
    float* Bsm = smem + STAGES*A_ELE;     // STAGES * B_ELE

    const int tid  = threadIdx.x;
    const int lane = tid & 31, warp = tid >> 5;
    const int g = lane >> 2, tg = lane & 3;
    const int wm = (warp >> 2) * 64;
    const int wn = (warp & 3)  * 32;

    /* adjacent CTAs share the same 128-column B panel (M-blocks 0..3) */
    const int  bid  = blockIdx.x;
    const int  bm   = (bid & 3) * 128;
    const long n0   = (long)(bid >> 2) * 128;
    const int  half = (n0 >= NHALF);
    const long rem  = n0 - (long)half * NHALF;
    const int  bb   = (int)(rem >> 12);
    const int  p0   = (int)(rem & 4095);
    const float* bsrc = (half ? xt : xc) + ((long)bb*CH)*HW + p0;

    const int arow = tid >> 2, ac4 = (tid & 3) * 4;
    const int brow = tid >> 5, bj  = (tid & 31) * 4;

    const float* aptr0 = g_W + (long)(bm + arow)      * CH + ac4;
    const float* aptr1 = g_W + (long)(bm + arow + 64) * CH + ac4;
    const float* bptr0 = bsrc + (long)brow     * HW + bj;
    const float* bptr1 = bsrc + (long)(brow+8) * HW + bj;

    unsigned sa0 = (unsigned)__cvta_generic_to_shared(Asm) + (arow*ASTRIDE + ac4)*4;
    unsigned sa1 = (unsigned)__cvta_generic_to_shared(Asm) + ((arow+64)*ASTRIDE + ac4)*4;
    unsigned sb0 = (unsigned)__cvta_generic_to_shared(Bsm) + (brow*BSTRIDE + bj)*4;
    unsigned sb1 = (unsigned)__cvta_generic_to_shared(Bsm) + ((brow+8)*BSTRIDE + bj)*4;

    auto issue = [&](int kt) {
        const int buf = kt % STAGES;
        const int k0  = kt * 16;
        unsigned ao = buf * (A_ELE*4), bo = buf * (B_ELE*4);
        asm volatile("cp.async.ca.shared.global [%0], [%1], 16;\n"
                     :: "r"(sa0 + ao), "l"(aptr0 + k0) : "memory");
        asm volatile("cp.async.ca.shared.global [%0], [%1], 16;\n"
                     :: "r"(sa1 + ao), "l"(aptr1 + k0) : "memory");
        asm volatile("cp.async.cg.shared.global [%0], [%1], 16;\n"
                     :: "r"(sb0 + bo), "l"(bptr0 + (long)k0*HW) : "memory");
        asm volatile("cp.async.cg.shared.global [%0], [%1], 16;\n"
                     :: "r"(sb1 + bo), "l"(bptr1 + (long)k0*HW) : "memory");
    };

    float acc[4][4][4];
    #pragma unroll
    for (int i = 0; i < 4; i++)
        #pragma unroll
        for (int j = 0; j < 4; j++)
            #pragma unroll
            for (int k = 0; k < 4; k++) acc[i][j][k] = 0.f;

    #pragma unroll
    for (int s = 0; s < STAGES-1; s++) {
        issue(s);
        asm volatile("cp.async.commit_group;\n" ::: "memory");
    }

    for (int kt = 0; kt < 32; kt++) {
        asm volatile("cp.async.wait_group %0;\n" :: "n"(STAGES-2) : "memory");
        __syncthreads();

        const int buf = kt % STAGES;
        const float* Asb = Asm + buf * A_ELE;
        const float* Bsb = Bsm + buf * B_ELE;

        #pragma unroll
        for (int kk = 0; kk < 16; kk += 8) {
            unsigned bf[4][2];
            #pragma unroll
            for (int nt = 0; nt < 4; nt++) {
                int col = wn + nt*8 + g;
                bf[nt][0] = tf32u(Bsb[(kk+tg  )*BSTRIDE + col]);
                bf[nt][1] = tf32u(Bsb[(kk+tg+4)*BSTRIDE + col]);
            }
            #pragma unroll
            for (int mt = 0; mt < 4; mt++) {
                int row = wm + mt*16;
                unsigned a0 = __float_as_uint(Asb[(row+g  )*ASTRIDE + kk+tg  ]);
                unsigned a1 = __float_as_uint(Asb[(row+g+8)*ASTRIDE + kk+tg  ]);
                unsigned a2 = __float_as_uint(Asb[(row+g  )*ASTRIDE + kk+tg+4]);
                unsigned a3 = __float_as_uint(Asb[(row+g+8)*ASTRIDE + kk+tg+4]);
                #pragma unroll
                for (int nt = 0; nt < 4; nt++) {
                    asm volatile(
                        "mma.sync.aligned.m16n8k8.row.col.f32.tf32.tf32.f32 "
                        "{%0,%1,%2,%3}, {%4,%5,%6,%7}, {%8,%9}, {%0,%1,%2,%3};\n"
                        : "+f"(acc[mt][nt][0]), "+f"(acc[mt][nt][1]),
                          "+f"(acc[mt][nt][2]), "+f"(acc[mt][nt][3])
                        : "r"(a0), "r"(a1), "r"(a2), "r"(a3),
                          "r"(bf[nt][0]), "r"(bf[nt][1]));
                }
            }
        }
        int nk = kt + STAGES - 1;
        if (nk < 32) issue(nk);
        asm volatile("cp.async.commit_group;\n" ::: "memory");
    }

    /* ---------------- fused epilogue ---------------- */
    const float* attp = (half ? g_att_c : g_att_t) + bb*CH;
    const float* xo   = half ? xc : xt;
    float*       op   = out + (half ? OUT_HALF : 0);

    float attv[4][2], mkv[4][2];
    #pragma unroll
    for (int mt = 0; mt < 4; mt++)
        #pragma unroll
        for (int h2 = 0; h2 < 2; h2++) {
            int mrow = bm + wm + mt*16 + g + h2*8;
            attv[mt][h2] = attp[mrow];
            mkv[mt][h2]  = half ? 0.f : g_mask[bb*CH + mrow];
        }

    #pragma unroll
    for (int mt = 0; mt < 4; mt++) {
        #pragma unroll
        for (int h2 = 0; h2 < 2; h2++) {
            int  mrow = bm + wm + mt*16 + g + h2*8;
            long base = ((long)bb*CH + mrow)*HW + p0;
            #pragma unroll
            for (int nt = 0; nt < 4; nt++) {
                int  col = wn + nt*8 + 2*tg;
                long idx = base + col;
                float2 xv = *(const float2*)(xo + idx);
                float c0 = acc[mt][nt][h2*2 + 0];
                float c1 = acc[mt][nt][h2*2 + 1];
                float2 o;
                if (!half) {
                    float a = attv[mt][h2], mk = mkv[mt][h2];
                    o.x = xv.x * a + mk * c0;
                    o.y = xv.y * a + mk * c1;
                } else {
                    float a = attv[mt][h2];
                    o.x = a * (xv.x + c0);
                    o.y = a * (xv.y + c1);
                }
                *(float2*)(op + idx) = o;
            }
        }
    }
}

/* ------------------------------------------------------------------ */
extern "C" void kernel_launch(void* const* d_in, const int* in_sizes, int n_in,
                              void* d_out, int out_size) {
    const float* x_t  = (const float*)d_in[0];
    const float* x_c  = (const float*)d_in[1];
    const float* w1_t = (const float*)d_in[2];
    const float* b1_t = (const float*)d_in[3];
    const float* w2_t = (const float*)d_in[4];
    const float* b2_t = (const float*)d_in[5];
    const float* w1_c = (const float*)d_in[6];
    const float* b1_c = (const float*)d_in[7];
    const float* w2_c = (const float*)d_in[8];
    const float* b2_c = (const float*)d_in[9];
    const float* ca   = (const float*)d_in[10];
    float* out = (float*)d_out;

    static int smem_set = 0;
    if (!smem_set) {
        cudaFuncSetAttribute(gemm_fused,
                             cudaFuncAttributeMaxDynamicSharedMemorySize,
                             SMEM_BYTES);
        smem_set = 1;
    }

    mean_kernel<<<2048, 256>>>(x_t, x_c);
    softmax_kernel<<<CH, 256>>>(ca);
    se_kernel<<<BATCH, 512>>>(w1_t, b1_t, w2_t, b2_t, w1_c, b1_c, w2_c, b2_c);
    gemm_fused<<<4096, 256, SMEM_BYTES>>>(x_t, x_c, out);
}

// round 8
// speedup vs baseline: 1.2946x; 1.1254x over previous
#include <cuda_runtime.h>
#include <math.h>
#include <stdint.h>

#define BATCH 16
#define CH    512
#define HW    4096
#define HID   32
#define KSEL  153
#define OUT_HALF ((long)BATCH*CH*HW)

#define STAGES  4
#define ASTRIDE 24
#define BSTRIDE 136
#define A_ELE   (128*ASTRIDE)   /* 3072 floats per stage */
#define B_ELE   (16*BSTRIDE)    /* 2176 floats per stage */
#define SMEM_BYTES (STAGES*(A_ELE+B_ELE)*4)

__device__ float g_W[CH*CH];          /* softmax rows, k-permuted in 16-groups */
__device__ float g_mean_t[BATCH*CH];
__device__ float g_mean_c[BATCH*CH];
__device__ float g_att_t[BATCH*CH];
__device__ float g_att_c[BATCH*CH];
__device__ int   g_gidx[BATCH*256];   /* 153 selected + 103 fill rows */
__device__ int   g_rem [BATCH*256];   /* remaining 256 rows: out=att*x  */

__device__ __forceinline__ float tf32r(float x) {
    unsigned u; asm("cvt.rna.tf32.f32 %0, %1;" : "=r"(u) : "f"(x));
    return __uint_as_float(u);
}
__device__ __forceinline__ unsigned tf32u(float x) {
    unsigned u; asm("cvt.rna.tf32.f32 %0, %1;" : "=r"(u) : "f"(x));
    return u;
}

/* ---------------- 1. spatial means ---------------- */
__global__ void mean_kernel(const float* __restrict__ xt,
                            const float* __restrict__ xc) {
    int row = blockIdx.x * 8 + (threadIdx.x >> 5);
    int lane = threadIdx.x & 31;
    int which = row >> 13, r = row & 8191;
    const float4* p = (const float4*)((which ? xc : xt) + (long)r * HW);
    float s = 0.f;
    #pragma unroll
    for (int i = 0; i < 32; i++) {
        float4 v = p[lane + 32*i];
        s += (v.x + v.y) + (v.z + v.w);
    }
    for (int o = 16; o; o >>= 1) s += __shfl_xor_sync(0xffffffffu, s, o);
    if (lane == 0) (which ? g_mean_c : g_mean_t)[r] = s * (1.f/HW);
}

/* ---------------- 2. SE MLPs + top-k lists ---------------- */
__global__ void se_kernel(const float* __restrict__ w1_t, const float* __restrict__ b1_t,
                          const float* __restrict__ w2_t, const float* __restrict__ b2_t,
                          const float* __restrict__ w1_c, const float* __restrict__ b1_c,
                          const float* __restrict__ w2_c, const float* __restrict__ b2_c) {
    int b = blockIdx.x, tid = threadIdx.x;   /* 512 threads */
    int warp = tid >> 5, lane = tid & 31;
    __shared__ float m[2][CH];
    __shared__ float h[2][HID];
    __shared__ float at[CH];
    __shared__ int   msk[CH];
    m[0][tid] = g_mean_t[b*CH + tid];
    m[1][tid] = g_mean_c[b*CH + tid];
    __syncthreads();
    for (int q = warp; q < 64; q += 16) {
        int br = q >> 5, j = q & 31;
        const float* w1 = br ? w1_c : w1_t;
        float s = 0.f;
        for (int i = lane; i < CH; i += 32) s += m[br][i] * w1[i*HID + j];
        for (int o = 16; o; o >>= 1) s += __shfl_xor_sync(0xffffffffu, s, o);
        if (lane == 0) h[br][j] = fmaxf(s + (br ? b1_c : b1_t)[j], 0.f);
    }
    __syncthreads();
    {
        float s0 = b2_t[tid], s1 = b2_c[tid];
        #pragma unroll
        for (int j = 0; j < HID; j++) {
            s0 += h[0][j] * w2_t[j*CH + tid];
            s1 += h[1][j] * w2_c[j*CH + tid];
        }
        float a0 = 1.f/(1.f + expf(-s0)), a1 = 1.f/(1.f + expf(-s1));
        at[tid] = a0;
        g_att_t[b*CH + tid] = a0;
        g_att_c[b*CH + tid] = a1;
    }
    __syncthreads();
    int sel;
    {   /* top-k membership: rank with lower-index tie-break (matches top_k) */
        float v = at[tid];
        int rank = 0;
        for (int j = 0; j < CH; j++) {
            float u = at[j];
            rank += (u > v) || (u == v && j < tid);
        }
        sel = (rank < KSEL);
        msk[tid] = sel;
    }
    __syncthreads();
    {   /* compact lists */
        int pre = 0;
        for (int j = 0; j < tid; j++) pre += msk[j];
        if (sel) g_gidx[b*256 + pre] = tid;
        else {
            int np = tid - pre;                 /* # non-selected before */
            if (np < 256 - KSEL) g_gidx[b*256 + KSEL + np] = tid;
            else                 g_rem [b*256 + np - (256 - KSEL)] = tid;
        }
    }
}

/* ---------------- 3. softmax -> permuted g_W ---------------- */
__device__ __forceinline__ int kperm(int c) {
    return (c & ~15) | ((c & 8) + 2*(c & 3) + ((c & 7) >> 2));
}
__global__ void softmax_kernel(const float* __restrict__ ca) {
    int r = blockIdx.x, tid = threadIdx.x;   /* 256 */
    __shared__ float red[8];
    float v0 = ca[r*CH + tid], v1 = ca[r*CH + 256 + tid];
    float mx = fmaxf(v0, v1);
    for (int o = 16; o; o >>= 1) mx = fmaxf(mx, __shfl_xor_sync(0xffffffffu, mx, o));
    if ((tid & 31) == 0) red[tid >> 5] = mx;
    __syncthreads();
    float m2 = red[0];
    #pragma unroll
    for (int i = 1; i < 8; i++) m2 = fmaxf(m2, red[i]);
    float e0 = expf(v0 - m2), e1 = expf(v1 - m2);
    float s = e0 + e1;
    for (int o = 16; o; o >>= 1) s += __shfl_xor_sync(0xffffffffu, s, o);
    __syncthreads();
    if ((tid & 31) == 0) red[tid >> 5] = s;
    __syncthreads();
    float tot = 0.f;
    #pragma unroll
    for (int i = 0; i < 8; i++) tot += red[i];
    float inv = 1.f / tot;
    g_W[r*CH + kperm(tid)]       = tf32r(e0 * inv);
    g_W[r*CH + kperm(tid + 256)] = tf32r(e1 * inv);
}

/* ---------------- 4. remainder rows: out_t = att*x ---------------- */
__global__ void rem_kernel(const float* __restrict__ xt, float* __restrict__ out) {
    int b = blockIdx.x >> 8, i = blockIdx.x & 255;
    int ch = g_rem[b*256 + i];
    float a = g_att_t[b*CH + ch];
    const float4* src = (const float4*)(xt + ((long)b*CH + ch)*HW);
    float4* dst = (float4*)(out + ((long)b*CH + ch)*HW);
    #pragma unroll
    for (int k = 0; k < 4; k++) {
        float4 v = src[threadIdx.x + 256*k];
        v.x *= a; v.y *= a; v.z *= a; v.w *= a;
        dst[threadIdx.x + 256*k] = v;
    }
}

/* ---------------- 5. fused GEMM ---------------- */
__global__ __launch_bounds__(256, 2)
void gemm_fused(const float* __restrict__ xt,
                const float* __restrict__ xc,
                float* __restrict__ out) {
    extern __shared__ float smem[];
    float* Asm = smem;
    float* Bsm = smem + STAGES*A_ELE;
    __shared__ int gtab[128];

    const int tid  = threadIdx.x;
    const int lane = tid & 31, warp = tid >> 5;
    const int g = lane >> 2, tg = lane & 3;
    const int wm = (warp >> 2) * 64;
    const int wn = (warp & 3)  * 32;

    /* grid: [0,1024) t-half (sparse, B=x_c), [1024,3072) c-half (B=x_t) */
    const int bid = blockIdx.x;
    const int tH  = bid < 1024;
    int panel, bm;
    if (tH) { panel = bid >> 1;          bm = (bid & 1) * 128; }
    else    { int q = bid - 1024; panel = q >> 2; bm = (q & 3) * 128; }
    const int bb = panel >> 5, p0 = (panel & 31) * 128;
    const float* bsrc = (tH ? xc : xt) + ((long)bb*CH)*HW + p0;
    const float* xe   = tH ? xt : xc;
    float*       op   = out + (tH ? 0 : OUT_HALF);

    if (tid < 128) gtab[tid] = tH ? g_gidx[bb*256 + bm + tid] : (bm + tid);
    __syncthreads();

    const int arow = tid >> 2, ac4 = (tid & 3) * 4;
    const int brow = tid >> 5, bj  = (tid & 31) * 4;
    const float* aptr0 = g_W + (long)gtab[arow]      * CH + ac4;
    const float* aptr1 = g_W + (long)gtab[arow + 64] * CH + ac4;
    const float* bptr0 = bsrc + (long)brow     * HW + bj;
    const float* bptr1 = bsrc + (long)(brow+8) * HW + bj;

    unsigned sa0 = (unsigned)__cvta_generic_to_shared(Asm) + (arow*ASTRIDE + ac4)*4;
    unsigned sa1 = (unsigned)__cvta_generic_to_shared(Asm) + ((arow+64)*ASTRIDE + ac4)*4;
    unsigned sb0 = (unsigned)__cvta_generic_to_shared(Bsm) + (brow*BSTRIDE + bj)*4;
    unsigned sb1 = (unsigned)__cvta_generic_to_shared(Bsm) + ((brow+8)*BSTRIDE + bj)*4;

    auto issue = [&](int kt) {
        const int buf = kt % STAGES;
        const int k0  = kt * 16;
        unsigned ao = buf * (A_ELE*4), bo = buf * (B_ELE*4);
        asm volatile("cp.async.ca.shared.global [%0], [%1], 16;\n"
                     :: "r"(sa0 + ao), "l"(aptr0 + k0) : "memory");
        asm volatile("cp.async.ca.shared.global [%0], [%1], 16;\n"
                     :: "r"(sa1 + ao), "l"(aptr1 + k0) : "memory");
        asm volatile("cp.async.cg.shared.global [%0], [%1], 16;\n"
                     :: "r"(sb0 + bo), "l"(bptr0 + (long)k0*HW) : "memory");
        asm volatile("cp.async.cg.shared.global [%0], [%1], 16;\n"
                     :: "r"(sb1 + bo), "l"(bptr1 + (long)k0*HW) : "memory");
    };

    float acc[4][4][4];
    #pragma unroll
    for (int i = 0; i < 4; i++)
        #pragma unroll
        for (int j = 0; j < 4; j++)
            #pragma unroll
            for (int k = 0; k < 4; k++) acc[i][j][k] = 0.f;

    #pragma unroll
    for (int s = 0; s < STAGES-1; s++) {
        issue(s);
        asm volatile("cp.async.commit_group;\n" ::: "memory");
    }

    for (int kt = 0; kt < 32; kt++) {
        asm volatile("cp.async.wait_group %0;\n" :: "n"(STAGES-2) : "memory");
        __syncthreads();

        const int buf = kt % STAGES;
        const float* Asb = Asm + buf * A_ELE;
        const float* Bsb = Bsm + buf * B_ELE;

        #pragma unroll
        for (int kko = 0; kko < 16; kko += 8) {
            unsigned bf[4][2];
            #pragma unroll
            for (int nt = 0; nt < 4; nt++) {
                int col = wn + nt*8 + g;
                bf[nt][0] = tf32u(Bsb[(kko+tg  )*BSTRIDE + col]);
                bf[nt][1] = tf32u(Bsb[(kko+tg+4)*BSTRIDE + col]);
            }
            #pragma unroll
            for (int mt = 0; mt < 4; mt++) {
                int row = wm + mt*16;
                /* permuted-k layout: logical cols {tg, tg+4} adjacent */
                float2 lo = *(const float2*)&Asb[(row+g  )*ASTRIDE + kko + 2*tg];
                float2 hi = *(const float2*)&Asb[(row+g+8)*ASTRIDE + kko + 2*tg];
                unsigned a0 = __float_as_uint(lo.x), a1 = __float_as_uint(hi.x);
                unsigned a2 = __float_as_uint(lo.y), a3 = __float_as_uint(hi.y);
                #pragma unroll
                for (int nt = 0; nt < 4; nt++) {
                    asm volatile(
                        "mma.sync.aligned.m16n8k8.row.col.f32.tf32.tf32.f32 "
                        "{%0,%1,%2,%3}, {%4,%5,%6,%7}, {%8,%9}, {%0,%1,%2,%3};\n"
                        : "+f"(acc[mt][nt][0]), "+f"(acc[mt][nt][1]),
                          "+f"(acc[mt][nt][2]), "+f"(acc[mt][nt][3])
                        : "r"(a0), "r"(a1), "r"(a2), "r"(a3),
                          "r"(bf[nt][0]), "r"(bf[nt][1]));
                }
            }
        }
        int nk = kt + STAGES - 1;
        if (nk < 32) issue(nk);
        asm volatile("cp.async.commit_group;\n" ::: "memory");
    }

    /* ---------------- epilogue: o = fs*x + fc*d ---------------- */
    const float* attp = (tH ? g_att_t : g_att_c) + bb*CH;

    #pragma unroll
    for (int mt = 0; mt < 4; mt++) {
        #pragma unroll
        for (int h2 = 0; h2 < 2; h2++) {
            int  local = wm + mt*16 + g + h2*8;
            int  ch    = gtab[local];
            float fs   = attp[ch];
            float fc   = tH ? ((bm + local) < KSEL ? 1.f : 0.f) : fs;
            long base  = ((long)bb*CH + ch)*HW + p0;
            #pragma unroll
            for (int nt = 0; nt < 4; nt++) {
                int  col = wn + nt*8 + 2*tg;
                long idx = base + col;
                float2 xv = *(const float2*)(xe + idx);
                float2 o;
                o.x = fs * xv.x + fc * acc[mt][nt][h2*2 + 0];
                o.y = fs * xv.y + fc * acc[mt][nt][h2*2 + 1];
                *(float2*)(op + idx) = o;
            }
        }
    }
}

/* ---------------- launch ---------------- */
extern "C" void kernel_launch(void* const* d_in, const int* in_sizes, int n_in,
                              void* d_out, int out_size) {
    const float* x_t  = (const float*)d_in[0];
    const float* x_c  = (const float*)d_in[1];
    const float* w1_t = (const float*)d_in[2];
    const float* b1_t = (const float*)d_in[3];
    const float* w2_t = (const float*)d_in[4];
    const float* b2_t = (const float*)d_in[5];
    const float* w1_c = (const float*)d_in[6];
    const float* b1_c = (const float*)d_in[7];
    const float* w2_c = (const float*)d_in[8];
    const float* b2_c = (const float*)d_in[9];
    const float* ca   = (const float*)d_in[10];
    float* out = (float*)d_out;

    static int init = 0;
    if (!init) {
        cudaFuncSetAttribute(gemm_fused,
                             cudaFuncAttributeMaxDynamicSharedMemorySize, SMEM_BYTES);
        init = 1;
    }
    mean_kernel<<<2048, 256>>>(x_t, x_c);
    softmax_kernel<<<CH, 256>>>(ca);
    se_kernel<<<BATCH, 512>>>(w1_t, b1_t, w2_t, b2_t, w1_c, b1_c, w2_c, b2_c);
    rem_kernel<<<BATCH*256, 256>>>(x_t, out);
    gemm_fused<<<3072, 256, SMEM_BYTES>>>(x_t, x_c, out);
}

// round 9
// speedup vs baseline: 1.4059x; 1.0860x over previous
#include <cuda_runtime.h>
#include <cuda_bf16.h>
#include <math.h>
#include <stdint.h>

#define BATCH 16
#define CH    512
#define HW    4096
#define HID   32
#define KSEL  153
#define OUT_HALF ((long)BATCH*CH*HW)

#define STAGES 4
#define BS     132                 /* B smem stride (floats) */
#define ASZ    4096                /* A stage bytes: 128 rows x 32B */
#define BELE   (16*BS)             /* B stage floats */
#define BSZB   (BELE*4)
#define SMEM_BYTES (STAGES*(ASZ + BSZB))

__device__ __nv_bfloat16 g_Wb[CH*CH];   /* softmax rows, bf16, k-permuted */
__device__ float g_mean_t[BATCH*CH];
__device__ float g_mean_c[BATCH*CH];
__device__ float g_att_t[BATCH*CH];
__device__ float g_att_c[BATCH*CH];
__device__ int   g_gidx[BATCH*256];
__device__ int   g_rem [BATCH*256];

/* ---------------- 1. spatial means ---------------- */
__global__ void mean_kernel(const float* __restrict__ xt,
                            const float* __restrict__ xc) {
    int row = blockIdx.x * 8 + (threadIdx.x >> 5);
    int lane = threadIdx.x & 31;
    int which = row >> 13, r = row & 8191;
    const float4* p = (const float4*)((which ? xc : xt) + (long)r * HW);
    float s = 0.f;
    #pragma unroll
    for (int i = 0; i < 32; i++) {
        float4 v = p[lane + 32*i];
        s += (v.x + v.y) + (v.z + v.w);
    }
    for (int o = 16; o; o >>= 1) s += __shfl_xor_sync(0xffffffffu, s, o);
    if (lane == 0) (which ? g_mean_c : g_mean_t)[r] = s * (1.f/HW);
}

/* ---------------- 2. SE MLPs + top-k lists ---------------- */
__global__ void se_kernel(const float* __restrict__ w1_t, const float* __restrict__ b1_t,
                          const float* __restrict__ w2_t, const float* __restrict__ b2_t,
                          const float* __restrict__ w1_c, const float* __restrict__ b1_c,
                          const float* __restrict__ w2_c, const float* __restrict__ b2_c) {
    int b = blockIdx.x, tid = threadIdx.x;   /* 512 threads */
    int warp = tid >> 5, lane = tid & 31;
    __shared__ float m[2][CH];
    __shared__ float h[2][HID];
    __shared__ float at[CH];
    __shared__ int   msk[CH];
    m[0][tid] = g_mean_t[b*CH + tid];
    m[1][tid] = g_mean_c[b*CH + tid];
    __syncthreads();
    for (int q = warp; q < 64; q += 16) {
        int br = q >> 5, j = q & 31;
        const float* w1 = br ? w1_c : w1_t;
        float s = 0.f;
        for (int i = lane; i < CH; i += 32) s += m[br][i] * w1[i*HID + j];
        for (int o = 16; o; o >>= 1) s += __shfl_xor_sync(0xffffffffu, s, o);
        if (lane == 0) h[br][j] = fmaxf(s + (br ? b1_c : b1_t)[j], 0.f);
    }
    __syncthreads();
    {
        float s0 = b2_t[tid], s1 = b2_c[tid];
        #pragma unroll
        for (int j = 0; j < HID; j++) {
            s0 += h[0][j] * w2_t[j*CH + tid];
            s1 += h[1][j] * w2_c[j*CH + tid];
        }
        float a0 = 1.f/(1.f + expf(-s0)), a1 = 1.f/(1.f + expf(-s1));
        at[tid] = a0;
        g_att_t[b*CH + tid] = a0;
        g_att_c[b*CH + tid] = a1;
    }
    __syncthreads();
    int sel;
    {
        float v = at[tid];
        int rank = 0;
        for (int j = 0; j < CH; j++) {
            float u = at[j];
            rank += (u > v) || (u == v && j < tid);
        }
        sel = (rank < KSEL);
        msk[tid] = sel;
    }
    __syncthreads();
    {
        int pre = 0;
        for (int j = 0; j < tid; j++) pre += msk[j];
        if (sel) g_gidx[b*256 + pre] = tid;
        else {
            int np = tid - pre;
            if (np < 256 - KSEL) g_gidx[b*256 + KSEL + np] = tid;
            else                 g_rem [b*256 + np - (256 - KSEL)] = tid;
        }
    }
}

/* ---------------- 3. softmax -> bf16 permuted g_Wb ----------------
   stored pos within each 16-group: group(bits2:1)*4 + hi(bit3)*2 + sub(bit0) */
__device__ __forceinline__ int kperm(int c) {
    return (c & ~15) | ((((c >> 1) & 3) << 2) | (((c >> 3) & 1) << 1) | (c & 1));
}
__global__ void softmax_kernel(const float* __restrict__ ca) {
    int r = blockIdx.x, tid = threadIdx.x;   /* 256 */
    __shared__ float red[8];
    float v0 = ca[r*CH + tid], v1 = ca[r*CH + 256 + tid];
    float mx = fmaxf(v0, v1);
    for (int o = 16; o; o >>= 1) mx = fmaxf(mx, __shfl_xor_sync(0xffffffffu, mx, o));
    if ((tid & 31) == 0) red[tid >> 5] = mx;
    __syncthreads();
    float m2 = red[0];
    #pragma unroll
    for (int i = 1; i < 8; i++) m2 = fmaxf(m2, red[i]);
    float e0 = expf(v0 - m2), e1 = expf(v1 - m2);
    float s = e0 + e1;
    for (int o = 16; o; o >>= 1) s += __shfl_xor_sync(0xffffffffu, s, o);
    __syncthreads();
    if ((tid & 31) == 0) red[tid >> 5] = s;
    __syncthreads();
    float tot = 0.f;
    #pragma unroll
    for (int i = 0; i < 8; i++) tot += red[i];
    float inv = 1.f / tot;
    g_Wb[r*CH + kperm(tid)]       = __float2bfloat16(e0 * inv);
    g_Wb[r*CH + kperm(tid + 256)] = __float2bfloat16(e1 * inv);
}

/* ---------------- 4. remainder rows: out_t = att*x ---------------- */
__global__ void rem_kernel(const float* __restrict__ xt, float* __restrict__ out) {
    int b = blockIdx.x >> 8, i = blockIdx.x & 255;
    int ch = g_rem[b*256 + i];
    float a = g_att_t[b*CH + ch];
    const float4* src = (const float4*)(xt + ((long)b*CH + ch)*HW);
    float4* dst = (float4*)(out + ((long)b*CH + ch)*HW);
    #pragma unroll
    for (int k = 0; k < 4; k++) {
        float4 v = src[threadIdx.x + 256*k];
        v.x *= a; v.y *= a; v.z *= a; v.w *= a;
        dst[threadIdx.x + 256*k] = v;
    }
}

/* ---------------- 5. fused bf16 GEMM ---------------- */
__global__ __launch_bounds__(256, 2)
void gemm_fused(const float* __restrict__ xt,
                const float* __restrict__ xc,
                float* __restrict__ out) {
    extern __shared__ char smem[];
    char*  Achar = smem;                       /* STAGES * ASZ bytes   */
    float* Bsm   = (float*)(smem + STAGES*ASZ);/* STAGES * BELE floats */
    __shared__ int gtab[128];

    const int tid  = threadIdx.x;
    const int lane = tid & 31, warp = tid >> 5;
    const int g = lane >> 2, tg = lane & 3;
    const int wm = (warp >> 2) * 64;
    const int wn = (warp & 3)  * 32;

    /* grid: [0,1024) t-half (sparse, B=x_c), [1024,3072) c-half (B=x_t) */
    const int bid = blockIdx.x;
    const int tH  = bid < 1024;
    int panel, bm;
    if (tH) { panel = bid >> 1;          bm = (bid & 1) * 128; }
    else    { int q = bid - 1024; panel = q >> 2; bm = (q & 3) * 128; }
    const int bb = panel >> 5, p0 = (panel & 31) * 128;
    const float* bsrc = (tH ? xc : xt) + ((long)bb*CH)*HW + p0;
    const float* xe   = tH ? xt : xc;
    float*       op   = out + (tH ? 0 : OUT_HALF);

    if (tid < 128) gtab[tid] = tH ? g_gidx[bb*256 + bm + tid] : (bm + tid);
    __syncthreads();

    /* A loader: thread -> (row = tid>>1, half = tid&1), 2 x 8B cp.async */
    const int arow = tid >> 1, ah = tid & 1;
    const __nv_bfloat16* aptr = g_Wb + (long)gtab[arow]*CH + ah*8;
    const unsigned abase = (unsigned)__cvta_generic_to_shared(Achar) + arow*32;
    const unsigned asa0 = abase + ((ah*16)     ^ ((arow & 3) * 8));
    const unsigned asa1 = abase + ((ah*16 + 8) ^ ((arow & 3) * 8));

    /* B loader: unchanged pattern, stride BS */
    const int brow = tid >> 5, bj = (tid & 31) * 4;
    const float* bptr0 = bsrc + (long)brow     * HW + bj;
    const float* bptr1 = bsrc + (long)(brow+8) * HW + bj;
    const unsigned sb0 = (unsigned)__cvta_generic_to_shared(Bsm) + (brow*BS + bj)*4;
    const unsigned sb1 = (unsigned)__cvta_generic_to_shared(Bsm) + ((brow+8)*BS + bj)*4;

    auto issue = [&](int kt) {
        const int buf = kt % STAGES;
        const int k0  = kt * 16;
        unsigned ao = buf * ASZ, bo = buf * BSZB;
        asm volatile("cp.async.ca.shared.global [%0], [%1], 8;\n"
                     :: "r"(asa0 + ao), "l"(aptr + k0) : "memory");
        asm volatile("cp.async.ca.shared.global [%0], [%1], 8;\n"
                     :: "r"(asa1 + ao), "l"(aptr + k0 + 4) : "memory");
        asm volatile("cp.async.cg.shared.global [%0], [%1], 16;\n"
                     :: "r"(sb0 + bo), "l"(bptr0 + (long)k0*HW) : "memory");
        asm volatile("cp.async.cg.shared.global [%0], [%1], 16;\n"
                     :: "r"(sb1 + bo), "l"(bptr1 + (long)k0*HW) : "memory");
    };

    float acc[4][4][4];
    #pragma unroll
    for (int i = 0; i < 4; i++)
        #pragma unroll
        for (int j = 0; j < 4; j++)
            #pragma unroll
            for (int k = 0; k < 4; k++) acc[i][j][k] = 0.f;

    #pragma unroll
    for (int s = 0; s < STAGES-1; s++) {
        issue(s);
        asm volatile("cp.async.commit_group;\n" ::: "memory");
    }

    const int xa = (tg*8) ^ ((g & 3) * 8);   /* A fragment swizzle (row&3 == g&3) */

    for (int kt = 0; kt < 32; kt++) {
        asm volatile("cp.async.wait_group %0;\n" :: "n"(STAGES-2) : "memory");
        __syncthreads();

        const int buf = kt % STAGES;
        const char*  Asb = Achar + buf * ASZ;
        const float* Bsb = Bsm + buf * BELE;

        /* B fragments: 4 floats per nt -> 2 bf16x2 regs */
        unsigned bf[4][2];
        #pragma unroll
        for (int nt = 0; nt < 4; nt++) {
            int col = wn + nt*8 + g;
            float f0 = Bsb[(2*tg    )*BS + col];
            float f1 = Bsb[(2*tg + 1)*BS + col];
            float f2 = Bsb[(2*tg + 8)*BS + col];
            float f3 = Bsb[(2*tg + 9)*BS + col];
            asm("cvt.rn.bf16x2.f32 %0, %1, %2;" : "=r"(bf[nt][0]) : "f"(f1), "f"(f0));
            asm("cvt.rn.bf16x2.f32 %0, %1, %2;" : "=r"(bf[nt][1]) : "f"(f3), "f"(f2));
        }
        #pragma unroll
        for (int mt = 0; mt < 4; mt++) {
            int row = wm + mt*16 + g;
            uint2 lo = *(const uint2*)(Asb + row*32 + xa);
            uint2 hi = *(const uint2*)(Asb + (row+8)*32 + xa);
            #pragma unroll
            for (int nt = 0; nt < 4; nt++) {
                asm volatile(
                    "mma.sync.aligned.m16n8k16.row.col.f32.bf16.bf16.f32 "
                    "{%0,%1,%2,%3}, {%4,%5,%6,%7}, {%8,%9}, {%0,%1,%2,%3};\n"
                    : "+f"(acc[mt][nt][0]), "+f"(acc[mt][nt][1]),
                      "+f"(acc[mt][nt][2]), "+f"(acc[mt][nt][3])
                    : "r"(lo.x), "r"(hi.x), "r"(lo.y), "r"(hi.y),
                      "r"(bf[nt][0]), "r"(bf[nt][1]));
            }
        }
        int nk = kt + STAGES - 1;
        if (nk < 32) issue(nk);
        asm volatile("cp.async.commit_group;\n" ::: "memory");
    }

    /* ---------------- epilogue: o = fs*x + fc*d ---------------- */
    const float* attp = (tH ? g_att_t : g_att_c) + bb*CH;

    #pragma unroll
    for (int mt = 0; mt < 4; mt++) {
        #pragma unroll
        for (int h2 = 0; h2 < 2; h2++) {
            int  local = wm + mt*16 + g + h2*8;
            int  ch    = gtab[local];
            float fs   = attp[ch];
            float fc   = tH ? ((bm + local) < KSEL ? 1.f : 0.f) : fs;
            long base  = ((long)bb*CH + ch)*HW + p0;
            #pragma unroll
            for (int nt = 0; nt < 4; nt++) {
                int  col = wn + nt*8 + 2*tg;
                long idx = base + col;
                float2 xv = *(const float2*)(xe + idx);
                float2 o;
                o.x = fs * xv.x + fc * acc[mt][nt][h2*2 + 0];
                o.y = fs * xv.y + fc * acc[mt][nt][h2*2 + 1];
                *(float2*)(op + idx) = o;
            }
        }
    }
}

/* ---------------- launch ---------------- */
extern "C" void kernel_launch(void* const* d_in, const int* in_sizes, int n_in,
                              void* d_out, int out_size) {
    const float* x_t  = (const float*)d_in[0];
    const float* x_c  = (const float*)d_in[1];
    const float* w1_t = (const float*)d_in[2];
    const float* b1_t = (const float*)d_in[3];
    const float* w2_t = (const float*)d_in[4];
    const float* b2_t = (const float*)d_in[5];
    const float* w1_c = (const float*)d_in[6];
    const float* b1_c = (const float*)d_in[7];
    const float* w2_c = (const float*)d_in[8];
    const float* b2_c = (const float*)d_in[9];
    const float* ca   = (const float*)d_in[10];
    float* out = (float*)d_out;

    static int init = 0;
    if (!init) {
        cudaFuncSetAttribute(gemm_fused,
                             cudaFuncAttributeMaxDynamicSharedMemorySize, SMEM_BYTES);
        init = 1;
    }
    mean_kernel<<<2048, 256>>>(x_t, x_c);
    softmax_kernel<<<CH, 256>>>(ca);
    se_kernel<<<BATCH, 512>>>(w1_t, b1_t, w2_t, b2_t, w1_c, b1_c, w2_c, b2_c);
    rem_kernel<<<BATCH*256, 256>>>(x_t, out);
    gemm_fused<<<3072, 256, SMEM_BYTES>>>(x_t, x_c, out);
}

// round 10
// speedup vs baseline: 1.4063x; 1.0003x over previous
#include <cuda_runtime.h>
#include <cuda_bf16.h>
#include <math.h>
#include <stdint.h>

#define BATCH 16
#define CH    512
#define HW    4096
#define HID   32
#define KSEL  153
#define OUT_HALF ((long)BATCH*CH*HW)

#define STAGES 3
#define BS     132                  /* B smem stride (floats)            */
#define ASTG   8192                 /* A stage bytes: 2 subtiles x 4096  */
#define BSUB   (16*BS)              /* B subtile floats                  */
#define BSTG   (2*BSUB*4)           /* B stage bytes = 16896             */
#define STGB   (ASTG + BSTG)        /* per-stage bytes = 25088           */
#define SMEM_BYTES (STAGES*STGB)    /* 75264                             */

__device__ __nv_bfloat16 g_Wb[CH*CH];   /* softmax rows, bf16, k-permuted */
__device__ float g_mean_t[BATCH*CH];
__device__ float g_mean_c[BATCH*CH];
__device__ float g_att_t[BATCH*CH];
__device__ float g_att_c[BATCH*CH];
__device__ int   g_gidx[BATCH*256];
__device__ int   g_rem [BATCH*256];

/* ---------------- 1. spatial means ---------------- */
__global__ void mean_kernel(const float* __restrict__ xt,
                            const float* __restrict__ xc) {
    int row = blockIdx.x * 8 + (threadIdx.x >> 5);
    int lane = threadIdx.x & 31;
    int which = row >> 13, r = row & 8191;
    const float4* p = (const float4*)((which ? xc : xt) + (long)r * HW);
    float s = 0.f;
    #pragma unroll
    for (int i = 0; i < 32; i++) {
        float4 v = p[lane + 32*i];
        s += (v.x + v.y) + (v.z + v.w);
    }
    for (int o = 16; o; o >>= 1) s += __shfl_xor_sync(0xffffffffu, s, o);
    if (lane == 0) (which ? g_mean_c : g_mean_t)[r] = s * (1.f/HW);
}

/* ---------------- 2. SE MLPs + top-k lists ---------------- */
__global__ void se_kernel(const float* __restrict__ w1_t, const float* __restrict__ b1_t,
                          const float* __restrict__ w2_t, const float* __restrict__ b2_t,
                          const float* __restrict__ w1_c, const float* __restrict__ b1_c,
                          const float* __restrict__ w2_c, const float* __restrict__ b2_c) {
    int b = blockIdx.x, tid = threadIdx.x;   /* 512 threads */
    int warp = tid >> 5, lane = tid & 31;
    __shared__ float m[2][CH];
    __shared__ float h[2][HID];
    __shared__ float at[CH];
    __shared__ int   msk[CH];
    m[0][tid] = g_mean_t[b*CH + tid];
    m[1][tid] = g_mean_c[b*CH + tid];
    __syncthreads();
    for (int q = warp; q < 64; q += 16) {
        int br = q >> 5, j = q & 31;
        const float* w1 = br ? w1_c : w1_t;
        float s = 0.f;
        for (int i = lane; i < CH; i += 32) s += m[br][i] * w1[i*HID + j];
        for (int o = 16; o; o >>= 1) s += __shfl_xor_sync(0xffffffffu, s, o);
        if (lane == 0) h[br][j] = fmaxf(s + (br ? b1_c : b1_t)[j], 0.f);
    }
    __syncthreads();
    {
        float s0 = b2_t[tid], s1 = b2_c[tid];
        #pragma unroll
        for (int j = 0; j < HID; j++) {
            s0 += h[0][j] * w2_t[j*CH + tid];
            s1 += h[1][j] * w2_c[j*CH + tid];
        }
        float a0 = 1.f/(1.f + expf(-s0)), a1 = 1.f/(1.f + expf(-s1));
        at[tid] = a0;
        g_att_t[b*CH + tid] = a0;
        g_att_c[b*CH + tid] = a1;
    }
    __syncthreads();
    int sel;
    {
        float v = at[tid];
        int rank = 0;
        for (int j = 0; j < CH; j++) {
            float u = at[j];
            rank += (u > v) || (u == v && j < tid);
        }
        sel = (rank < KSEL);
        msk[tid] = sel;
    }
    __syncthreads();
    {
        int pre = 0;
        for (int j = 0; j < tid; j++) pre += msk[j];
        if (sel) g_gidx[b*256 + pre] = tid;
        else {
            int np = tid - pre;
            if (np < 256 - KSEL) g_gidx[b*256 + KSEL + np] = tid;
            else                 g_rem [b*256 + np - (256 - KSEL)] = tid;
        }
    }
}

/* ---------------- 3. softmax -> bf16 permuted g_Wb ---------------- */
__device__ __forceinline__ int kperm(int c) {
    return (c & ~15) | ((((c >> 1) & 3) << 2) | (((c >> 3) & 1) << 1) | (c & 1));
}
__global__ void softmax_kernel(const float* __restrict__ ca) {
    int r = blockIdx.x, tid = threadIdx.x;   /* 256 */
    __shared__ float red[8];
    float v0 = ca[r*CH + tid], v1 = ca[r*CH + 256 + tid];
    float mx = fmaxf(v0, v1);
    for (int o = 16; o; o >>= 1) mx = fmaxf(mx, __shfl_xor_sync(0xffffffffu, mx, o));
    if ((tid & 31) == 0) red[tid >> 5] = mx;
    __syncthreads();
    float m2 = red[0];
    #pragma unroll
    for (int i = 1; i < 8; i++) m2 = fmaxf(m2, red[i]);
    float e0 = expf(v0 - m2), e1 = expf(v1 - m2);
    float s = e0 + e1;
    for (int o = 16; o; o >>= 1) s += __shfl_xor_sync(0xffffffffu, s, o);
    __syncthreads();
    if ((tid & 31) == 0) red[tid >> 5] = s;
    __syncthreads();
    float tot = 0.f;
    #pragma unroll
    for (int i = 0; i < 8; i++) tot += red[i];
    float inv = 1.f / tot;
    g_Wb[r*CH + kperm(tid)]       = __float2bfloat16(e0 * inv);
    g_Wb[r*CH + kperm(tid + 256)] = __float2bfloat16(e1 * inv);
}

/* ---------------- 4. remainder rows: out_t = att*x ---------------- */
__global__ void rem_kernel(const float* __restrict__ xt, float* __restrict__ out) {
    int b = blockIdx.x >> 8, i = blockIdx.x & 255;
    int ch = g_rem[b*256 + i];
    float a = g_att_t[b*CH + ch];
    const float4* src = (const float4*)(xt + ((long)b*CH + ch)*HW);
    float4* dst = (float4*)(out + ((long)b*CH + ch)*HW);
    #pragma unroll
    for (int k = 0; k < 4; k++) {
        float4 v = src[threadIdx.x + 256*k];
        v.x *= a; v.y *= a; v.z *= a; v.w *= a;
        dst[threadIdx.x + 256*k] = v;
    }
}

/* ---------------- 5. fused bf16 GEMM (K=32 stages, frag pipelined) --- */
__global__ __launch_bounds__(256, 2)
void gemm_fused(const float* __restrict__ xt,
                const float* __restrict__ xc,
                float* __restrict__ out) {
    extern __shared__ char smem[];
    __shared__ int gtab[128];

    const int tid  = threadIdx.x;
    const int lane = tid & 31, warp = tid >> 5;
    const int g = lane >> 2, tg = lane & 3;
    const int wm = (warp >> 2) * 64;
    const int wn = (warp & 3)  * 32;

    const int bid = blockIdx.x;
    const int tH  = bid < 1024;
    int panel, bm;
    if (tH) { panel = bid >> 1;          bm = (bid & 1) * 128; }
    else    { int q = bid - 1024; panel = q >> 2; bm = (q & 3) * 128; }
    const int bb = panel >> 5, p0 = (panel & 31) * 128;
    const float* bsrc = (tH ? xc : xt) + ((long)bb*CH)*HW + p0;
    const float* xe   = tH ? xt : xc;
    float*       op   = out + (tH ? 0 : OUT_HALF);

    if (tid < 128) gtab[tid] = tH ? g_gidx[bb*256 + bm + tid] : (bm + tid);
    __syncthreads();

    /* A loader: row = tid>>1, half = tid&1; 2 x 8B cp.async per subtile */
    const int arow = tid >> 1, ah = tid & 1;
    const __nv_bfloat16* aptr = g_Wb + (long)gtab[arow]*CH + ah*8;
    const unsigned asw0 = arow*32 + ((ah*16)     ^ ((arow & 3) * 8));
    const unsigned asw1 = arow*32 + ((ah*16 + 8) ^ ((arow & 3) * 8));

    /* B loader: rows brow, brow+8 per subtile */
    const int brow = tid >> 5, bj = (tid & 31) * 4;
    const unsigned smbase = (unsigned)__cvta_generic_to_shared(smem);

    auto issue = [&](int st) {
        const int p  = st % STAGES;
        const int k0 = st * 32;
        const unsigned ab  = smbase + p*STGB;
        const unsigned bbs = ab + ASTG;
        #pragma unroll
        for (int j = 0; j < 2; j++) {
            const __nv_bfloat16* sA = aptr + k0 + j*16;
            asm volatile("cp.async.ca.shared.global [%0], [%1], 8;\n"
                         :: "r"(ab + j*4096 + asw0), "l"(sA) : "memory");
            asm volatile("cp.async.ca.shared.global [%0], [%1], 8;\n"
                         :: "r"(ab + j*4096 + asw1), "l"(sA + 4) : "memory");
            const float* b0 = bsrc + (long)(k0 + j*16 + brow)*HW + bj;
            const float* b1 = bsrc + (long)(k0 + j*16 + brow + 8)*HW + bj;
            asm volatile("cp.async.cg.shared.global [%0], [%1], 16;\n"
                         :: "r"(bbs + (j*BSUB + brow*BS + bj)*4), "l"(b0) : "memory");
            asm volatile("cp.async.cg.shared.global [%0], [%1], 16;\n"
                         :: "r"(bbs + (j*BSUB + (brow+8)*BS + bj)*4), "l"(b1) : "memory");
        }
    };

    float acc[4][4][4];
    #pragma unroll
    for (int i = 0; i < 4; i++)
        #pragma unroll
        for (int j = 0; j < 4; j++)
            #pragma unroll
            for (int k = 0; k < 4; k++) acc[i][j][k] = 0.f;

    issue(0);
    asm volatile("cp.async.commit_group;\n" ::: "memory");
    issue(1);
    asm volatile("cp.async.commit_group;\n" ::: "memory");

    const int xa = (tg*8) ^ ((g & 3) * 8);   /* A fragment swizzle */

    for (int st = 0; st < 16; st++) {
        asm volatile("cp.async.wait_group 1;\n" ::: "memory");
        __syncthreads();
        if (st < 14) issue(st + 2);
        asm volatile("cp.async.commit_group;\n" ::: "memory");

        const int p = st % STAGES;
        const char*  Asb = smem + p*STGB;
        const float* Bsb = (const float*)(Asb + ASTG);

        /* B fragments for subtile 0 */
        unsigned bf0[4][2], bf1[4][2];
        #pragma unroll
        for (int nt = 0; nt < 4; nt++) {
            int col = wn + nt*8 + g;
            float f0 = Bsb[(2*tg    )*BS + col];
            float f1 = Bsb[(2*tg + 1)*BS + col];
            float f2 = Bsb[(2*tg + 8)*BS + col];
            float f3 = Bsb[(2*tg + 9)*BS + col];
            asm("cvt.rn.bf16x2.f32 %0, %1, %2;" : "=r"(bf0[nt][0]) : "f"(f1), "f"(f0));
            asm("cvt.rn.bf16x2.f32 %0, %1, %2;" : "=r"(bf0[nt][1]) : "f"(f3), "f"(f2));
        }
        /* prefetch subtile-1 B fragments (overlaps subtile-0 MMAs) */
        #pragma unroll
        for (int nt = 0; nt < 4; nt++) {
            int col = wn + nt*8 + g;
            const float* B1 = Bsb + BSUB;
            float f0 = B1[(2*tg    )*BS + col];
            float f1 = B1[(2*tg + 1)*BS + col];
            float f2 = B1[(2*tg + 8)*BS + col];
            float f3 = B1[(2*tg + 9)*BS + col];
            asm("cvt.rn.bf16x2.f32 %0, %1, %2;" : "=r"(bf1[nt][0]) : "f"(f1), "f"(f0));
            asm("cvt.rn.bf16x2.f32 %0, %1, %2;" : "=r"(bf1[nt][1]) : "f"(f3), "f"(f2));
        }
        #pragma unroll
        for (int mt = 0; mt < 4; mt++) {
            int row = wm + mt*16 + g;
            uint2 lo = *(const uint2*)(Asb + row*32 + xa);
            uint2 hi = *(const uint2*)(Asb + (row+8)*32 + xa);
            #pragma unroll
            for (int nt = 0; nt < 4; nt++) {
                asm volatile(
                    "mma.sync.aligned.m16n8k16.row.col.f32.bf16.bf16.f32 "
                    "{%0,%1,%2,%3}, {%4,%5,%6,%7}, {%8,%9}, {%0,%1,%2,%3};\n"
                    : "+f"(acc[mt][nt][0]), "+f"(acc[mt][nt][1]),
                      "+f"(acc[mt][nt][2]), "+f"(acc[mt][nt][3])
                    : "r"(lo.x), "r"(hi.x), "r"(lo.y), "r"(hi.y),
                      "r"(bf0[nt][0]), "r"(bf0[nt][1]));
            }
        }
        #pragma unroll
        for (int mt = 0; mt < 4; mt++) {
            int row = wm + mt*16 + g;
            const char* A1 = Asb + 4096;
            uint2 lo = *(const uint2*)(A1 + row*32 + xa);
            uint2 hi = *(const uint2*)(A1 + (row+8)*32 + xa);
            #pragma unroll
            for (int nt = 0; nt < 4; nt++) {
                asm volatile(
                    "mma.sync.aligned.m16n8k16.row.col.f32.bf16.bf16.f32 "
                    "{%0,%1,%2,%3}, {%4,%5,%6,%7}, {%8,%9}, {%0,%1,%2,%3};\n"
                    : "+f"(acc[mt][nt][0]), "+f"(acc[mt][nt][1]),
                      "+f"(acc[mt][nt][2]), "+f"(acc[mt][nt][3])
                    : "r"(lo.x), "r"(hi.x), "r"(lo.y), "r"(hi.y),
                      "r"(bf1[nt][0]), "r"(bf1[nt][1]));
            }
        }
    }

    /* ---------------- epilogue: o = fs*x + fc*d ---------------- */
    const float* attp = (tH ? g_att_t : g_att_c) + bb*CH;

    #pragma unroll
    for (int mt = 0; mt < 4; mt++) {
        #pragma unroll
        for (int h2 = 0; h2 < 2; h2++) {
            int  local = wm + mt*16 + g + h2*8;
            int  ch    = gtab[local];
            float fs   = attp[ch];
            float fc   = tH ? ((bm + local) < KSEL ? 1.f : 0.f) : fs;
            long base  = ((long)bb*CH + ch)*HW + p0;
            #pragma unroll
            for (int nt = 0; nt < 4; nt++) {
                int  col = wn + nt*8 + 2*tg;
                long idx = base + col;
                float2 xv = *(const float2*)(xe + idx);
                float2 o;
                o.x = fs * xv.x + fc * acc[mt][nt][h2*2 + 0];
                o.y = fs * xv.y + fc * acc[mt][nt][h2*2 + 1];
                *(float2*)(op + idx) = o;
            }
        }
    }
}

/* ---------------- launch ---------------- */
extern "C" void kernel_launch(void* const* d_in, const int* in_sizes, int n_in,
                              void* d_out, int out_size) {
    const float* x_t  = (const float*)d_in[0];
    const float* x_c  = (const float*)d_in[1];
    const float* w1_t = (const float*)d_in[2];
    const float* b1_t = (const float*)d_in[3];
    const float* w2_t = (const float*)d_in[4];
    const float* b2_t = (const float*)d_in[5];
    const float* w1_c = (const float*)d_in[6];
    const float* b1_c = (const float*)d_in[7];
    const float* w2_c = (const float*)d_in[8];
    const float* b2_c = (const float*)d_in[9];
    const float* ca   = (const float*)d_in[10];
    float* out = (float*)d_out;

    static int init = 0;
    if (!init) {
        cudaFuncSetAttribute(gemm_fused,
                             cudaFuncAttributeMaxDynamicSharedMemorySize, SMEM_BYTES);
        init = 1;
    }
    mean_kernel<<<2048, 256>>>(x_t, x_c);
    softmax_kernel<<<CH, 256>>>(ca);
    se_kernel<<<BATCH, 512>>>(w1_t, b1_t, w2_t, b2_t, w1_c, b1_c, w2_c, b2_c);
    rem_kernel<<<BATCH*256, 256>>>(x_t, out);
    gemm_fused<<<3072, 256, SMEM_BYTES>>>(x_t, x_c, out);
}

// round 11
// speedup vs baseline: 1.5296x; 1.0877x over previous
#include <cuda_runtime.h>
#include <cuda_bf16.h>
#include <math.h>
#include <stdint.h>

#define BATCH 16
#define CH    512
#define HW    4096
#define HID   32
#define KSEL  153
#define OUT_HALF ((long)BATCH*CH*HW)

#define STAGES 4
#define BSN    136                  /* B smem n-stride (uint32 units)     */
#define ASTG   8192                 /* A stage bytes: 2 subtiles x 4096   */
#define BSTG   (16*BSN*4)           /* B stage bytes = 8704               */
#define STGB   (ASTG + BSTG)        /* 16896 per stage                    */
#define SMEM_BYTES (STAGES*STGB)    /* 67584                              */

__device__ __nv_bfloat16 g_Wb[CH*CH];       /* softmax rows, bf16, k-permuted */
__device__ uint32_t g_xbt[(long)BATCH*256*HW];  /* x_t bf16 pair-interleaved */
__device__ uint32_t g_xbc[(long)BATCH*256*HW];  /* x_c bf16 pair-interleaved */
__device__ float g_mean_t[BATCH*CH];
__device__ float g_mean_c[BATCH*CH];
__device__ float g_att_t[BATCH*CH];
__device__ float g_att_c[BATCH*CH];
__device__ int   g_gidx[BATCH*256];
__device__ int   g_rem [BATCH*256];

__device__ __forceinline__ uint32_t packbf(float lo, float hi) {
    uint32_t u;
    asm("cvt.rn.bf16x2.f32 %0, %1, %2;" : "=r"(u) : "f"(hi), "f"(lo));
    return u;
}

/* ------- 1. spatial means + bf16 pair-interleaved copy -------
   one warp per channel-PAIR: rows 2*r2, 2*r2+1 (r2 = b*256+c2)   */
__global__ void mean_kernel(const float* __restrict__ xt,
                            const float* __restrict__ xc) {
    int pr = blockIdx.x * 8 + (threadIdx.x >> 5);   /* 0..8191 */
    int lane = threadIdx.x & 31;
    int which = pr >> 12;                            /* 0: t, 1: c */
    int r2 = pr & 4095;                              /* b*256 + c2 */
    const float* src = which ? xc : xt;
    const float4* pa = (const float4*)(src + (long)(2*r2) * HW);
    const float4* pb = pa + HW/4;
    uint4* po = (uint4*)((which ? g_xbc : g_xbt) + (long)r2 * HW);
    float s0 = 0.f, s1 = 0.f;
    #pragma unroll
    for (int i = 0; i < 32; i++) {
        float4 a = pa[lane + 32*i];
        float4 b = pb[lane + 32*i];
        s0 += (a.x + a.y) + (a.z + a.w);
        s1 += (b.x + b.y) + (b.z + b.w);
        uint4 o;
        o.x = packbf(a.x, b.x);
        o.y = packbf(a.y, b.y);
        o.z = packbf(a.z, b.z);
        o.w = packbf(a.w, b.w);
        po[lane + 32*i] = o;
    }
    for (int o = 16; o; o >>= 1) {
        s0 += __shfl_xor_sync(0xffffffffu, s0, o);
        s1 += __shfl_xor_sync(0xffffffffu, s1, o);
    }
    if (lane == 0) {
        float* dst = which ? g_mean_c : g_mean_t;
        dst[2*r2]     = s0 * (1.f/HW);
        dst[2*r2 + 1] = s1 * (1.f/HW);
    }
}

/* ---------------- 2. SE MLPs + top-k lists ---------------- */
__global__ void se_kernel(const float* __restrict__ w1_t, const float* __restrict__ b1_t,
                          const float* __restrict__ w2_t, const float* __restrict__ b2_t,
                          const float* __restrict__ w1_c, const float* __restrict__ b1_c,
                          const float* __restrict__ w2_c, const float* __restrict__ b2_c) {
    int b = blockIdx.x, tid = threadIdx.x;   /* 512 threads */
    int warp = tid >> 5, lane = tid & 31;
    __shared__ float m[2][CH];
    __shared__ float h[2][HID];
    __shared__ float at[CH];
    __shared__ int   msk[CH];
    m[0][tid] = g_mean_t[b*CH + tid];
    m[1][tid] = g_mean_c[b*CH + tid];
    __syncthreads();
    for (int q = warp; q < 64; q += 16) {
        int br = q >> 5, j = q & 31;
        const float* w1 = br ? w1_c : w1_t;
        float s = 0.f;
        for (int i = lane; i < CH; i += 32) s += m[br][i] * w1[i*HID + j];
        for (int o = 16; o; o >>= 1) s += __shfl_xor_sync(0xffffffffu, s, o);
        if (lane == 0) h[br][j] = fmaxf(s + (br ? b1_c : b1_t)[j], 0.f);
    }
    __syncthreads();
    {
        float s0 = b2_t[tid], s1 = b2_c[tid];
        #pragma unroll
        for (int j = 0; j < HID; j++) {
            s0 += h[0][j] * w2_t[j*CH + tid];
            s1 += h[1][j] * w2_c[j*CH + tid];
        }
        float a0 = 1.f/(1.f + expf(-s0)), a1 = 1.f/(1.f + expf(-s1));
        at[tid] = a0;
        g_att_t[b*CH + tid] = a0;
        g_att_c[b*CH + tid] = a1;
    }
    __syncthreads();
    int sel;
    {
        float v = at[tid];
        int rank = 0;
        for (int j = 0; j < CH; j++) {
            float u = at[j];
            rank += (u > v) || (u == v && j < tid);
        }
        sel = (rank < KSEL);
        msk[tid] = sel;
    }
    __syncthreads();
    {
        int pre = 0;
        for (int j = 0; j < tid; j++) pre += msk[j];
        if (sel) g_gidx[b*256 + pre] = tid;
        else {
            int np = tid - pre;
            if (np < 256 - KSEL) g_gidx[b*256 + KSEL + np] = tid;
            else                 g_rem [b*256 + np - (256 - KSEL)] = tid;
        }
    }
}

/* ---------------- 3. softmax -> bf16 permuted g_Wb ---------------- */
__device__ __forceinline__ int kperm(int c) {
    return (c & ~15) | ((((c >> 1) & 3) << 2) | (((c >> 3) & 1) << 1) | (c & 1));
}
__global__ void softmax_kernel(const float* __restrict__ ca) {
    int r = blockIdx.x, tid = threadIdx.x;   /* 256 */
    __shared__ float red[8];
    float v0 = ca[r*CH + tid], v1 = ca[r*CH + 256 + tid];
    float mx = fmaxf(v0, v1);
    for (int o = 16; o; o >>= 1) mx = fmaxf(mx, __shfl_xor_sync(0xffffffffu, mx, o));
    if ((tid & 31) == 0) red[tid >> 5] = mx;
    __syncthreads();
    float m2 = red[0];
    #pragma unroll
    for (int i = 1; i < 8; i++) m2 = fmaxf(m2, red[i]);
    float e0 = expf(v0 - m2), e1 = expf(v1 - m2);
    float s = e0 + e1;
    for (int o = 16; o; o >>= 1) s += __shfl_xor_sync(0xffffffffu, s, o);
    __syncthreads();
    if ((tid & 31) == 0) red[tid >> 5] = s;
    __syncthreads();
    float tot = 0.f;
    #pragma unroll
    for (int i = 0; i < 8; i++) tot += red[i];
    float inv = 1.f / tot;
    g_Wb[r*CH + kperm(tid)]       = __float2bfloat16(e0 * inv);
    g_Wb[r*CH + kperm(tid + 256)] = __float2bfloat16(e1 * inv);
}

/* ---------------- 4. remainder rows: out_t = att*x ---------------- */
__global__ void rem_kernel(const float* __restrict__ xt, float* __restrict__ out) {
    int b = blockIdx.x >> 8, i = blockIdx.x & 255;
    int ch = g_rem[b*256 + i];
    float a = g_att_t[b*CH + ch];
    const float4* src = (const float4*)(xt + ((long)b*CH + ch)*HW);
    float4* dst = (float4*)(out + ((long)b*CH + ch)*HW);
    #pragma unroll
    for (int k = 0; k < 4; k++) {
        float4 v = src[threadIdx.x + 256*k];
        v.x *= a; v.y *= a; v.z *= a; v.w *= a;
        dst[threadIdx.x + 256*k] = v;
    }
}

/* -------- 5. fused bf16 GEMM: bf16 pair-packed B, K=32 stages -------- */
__global__ __launch_bounds__(256, 2)
void gemm_fused(const float* __restrict__ xt,
                const float* __restrict__ xc,
                float* __restrict__ out) {
    extern __shared__ char smem[];
    __shared__ int gtab[128];

    const int tid  = threadIdx.x;
    const int lane = tid & 31, warp = tid >> 5;
    const int g = lane >> 2, tg = lane & 3;
    const int wm = (warp >> 2) * 64;
    const int wn = (warp & 3)  * 32;

    const int bid = blockIdx.x;
    const int tH  = bid < 1024;
    int panel, bm;
    if (tH) { panel = bid >> 1;          bm = (bid & 1) * 128; }
    else    { int q = bid - 1024; panel = q >> 2; bm = (q & 3) * 128; }
    const int bb = panel >> 5, p0 = (panel & 31) * 128;
    const uint32_t* bsrc2 = (tH ? g_xbc : g_xbt) + (long)bb*256*HW + p0;
    const float* xe = tH ? xt : xc;
    float*       op = out + (tH ? 0 : OUT_HALF);

    if (tid < 128) gtab[tid] = tH ? g_gidx[bb*256 + bm + tid] : (bm + tid);
    __syncthreads();

    /* A loader: row = tid>>1, half = tid&1; 2 x 8B cp.async per subtile */
    const int arow = tid >> 1, ah = tid & 1;
    const __nv_bfloat16* aptr = g_Wb + (long)gtab[arow]*CH + ah*8;
    const unsigned asw0 = arow*32 + ((ah*16)     ^ ((arow & 3) * 8));
    const unsigned asw1 = arow*32 + ((ah*16 + 8) ^ ((arow & 3) * 8));

    /* B loader: 16 pair-rows x 512B per stage; 2 x 16B per thread */
    const int b2row = tid >> 4;            /* 0..15 */
    const int b2col = (tid & 15) * 8;      /* uint32 units */
    const unsigned smbase = (unsigned)__cvta_generic_to_shared(smem);

    auto issue = [&](int st) {
        const int p = st % STAGES;
        const unsigned ab  = smbase + p*STGB;
        const unsigned bbs = ab + ASTG;
        const int k0 = st * 32;
        #pragma unroll
        for (int j = 0; j < 2; j++) {
            const __nv_bfloat16* sA = aptr + k0 + j*16;
            asm volatile("cp.async.ca.shared.global [%0], [%1], 8;\n"
                         :: "r"(ab + j*4096 + asw0), "l"(sA) : "memory");
            asm volatile("cp.async.ca.shared.global [%0], [%1], 8;\n"
                         :: "r"(ab + j*4096 + asw1), "l"(sA + 4) : "memory");
        }
        const uint32_t* bp = bsrc2 + (long)(st*16 + b2row)*HW + b2col;
        const unsigned bd = bbs + (b2row*BSN + b2col)*4;
        asm volatile("cp.async.cg.shared.global [%0], [%1], 16;\n"
                     :: "r"(bd), "l"(bp) : "memory");
        asm volatile("cp.async.cg.shared.global [%0], [%1], 16;\n"
                     :: "r"(bd + 16), "l"(bp + 4) : "memory");
    };

    float acc[4][4][4];
    #pragma unroll
    for (int i = 0; i < 4; i++)
        #pragma unroll
        for (int j = 0; j < 4; j++)
            #pragma unroll
            for (int k = 0; k < 4; k++) acc[i][j][k] = 0.f;

    issue(0); asm volatile("cp.async.commit_group;\n" ::: "memory");
    issue(1); asm volatile("cp.async.commit_group;\n" ::: "memory");
    issue(2); asm volatile("cp.async.commit_group;\n" ::: "memory");

    const int xa = (tg*8) ^ ((g & 3) * 8);   /* A fragment swizzle */

    for (int st = 0; st < 16; st++) {
        asm volatile("cp.async.wait_group 2;\n" ::: "memory");
        __syncthreads();
        if (st < 13) issue(st + 3);
        asm volatile("cp.async.commit_group;\n" ::: "memory");

        const int p = st % STAGES;
        const char*     Asb = smem + p*STGB;
        const uint32_t* Bsb = (const uint32_t*)(Asb + ASTG);

        #pragma unroll
        for (int j = 0; j < 2; j++) {
            unsigned bf[4][2];
            #pragma unroll
            for (int nt = 0; nt < 4; nt++) {
                int col = wn + nt*8 + g;
                bf[nt][0] = Bsb[(j*8 + tg    )*BSN + col];
                bf[nt][1] = Bsb[(j*8 + tg + 4)*BSN + col];
            }
            const char* Aj = Asb + j*4096;
            #pragma unroll
            for (int mt = 0; mt < 4; mt++) {
                int row = wm + mt*16 + g;
                uint2 lo = *(const uint2*)(Aj + row*32 + xa);
                uint2 hi = *(const uint2*)(Aj + (row+8)*32 + xa);
                #pragma unroll
                for (int nt = 0; nt < 4; nt++) {
                    asm volatile(
                        "mma.sync.aligned.m16n8k16.row.col.f32.bf16.bf16.f32 "
                        "{%0,%1,%2,%3}, {%4,%5,%6,%7}, {%8,%9}, {%0,%1,%2,%3};\n"
                        : "+f"(acc[mt][nt][0]), "+f"(acc[mt][nt][1]),
                          "+f"(acc[mt][nt][2]), "+f"(acc[mt][nt][3])
                        : "r"(lo.x), "r"(hi.x), "r"(lo.y), "r"(hi.y),
                          "r"(bf[nt][0]), "r"(bf[nt][1]));
                }
            }
        }
    }

    /* ---------------- epilogue: o = fs*x + fc*d ---------------- */
    const float* attp = (tH ? g_att_t : g_att_c) + bb*CH;

    #pragma unroll
    for (int mt = 0; mt < 4; mt++) {
        #pragma unroll
        for (int h2 = 0; h2 < 2; h2++) {
            int  local = wm + mt*16 + g + h2*8;
            int  ch    = gtab[local];
            float fs   = attp[ch];
            float fc   = tH ? ((bm + local) < KSEL ? 1.f : 0.f) : fs;
            long base  = ((long)bb*CH + ch)*HW + p0;
            #pragma unroll
            for (int nt = 0; nt < 4; nt++) {
                int  col = wn + nt*8 + 2*tg;
                long idx = base + col;
                float2 xv = *(const float2*)(xe + idx);
                float2 o;
                o.x = fs * xv.x + fc * acc[mt][nt][h2*2 + 0];
                o.y = fs * xv.y + fc * acc[mt][nt][h2*2 + 1];
                *(float2*)(op + idx) = o;
            }
        }
    }
}

/* ---------------- launch ---------------- */
extern "C" void kernel_launch(void* const* d_in, const int* in_sizes, int n_in,
                              void* d_out, int out_size) {
    const float* x_t  = (const float*)d_in[0];
    const float* x_c  = (const float*)d_in[1];
    const float* w1_t = (const float*)d_in[2];
    const float* b1_t = (const float*)d_in[3];
    const float* w2_t = (const float*)d_in[4];
    const float* b2_t = (const float*)d_in[5];
    const float* w1_c = (const float*)d_in[6];
    const float* b1_c = (const float*)d_in[7];
    const float* w2_c = (const float*)d_in[8];
    const float* b2_c = (const float*)d_in[9];
    const float* ca   = (const float*)d_in[10];
    float* out = (float*)d_out;

    static int init = 0;
    if (!init) {
        cudaFuncSetAttribute(gemm_fused,
                             cudaFuncAttributeMaxDynamicSharedMemorySize, SMEM_BYTES);
        init = 1;
    }
    mean_kernel<<<1024, 256>>>(x_t, x_c);
    softmax_kernel<<<CH, 256>>>(ca);
    se_kernel<<<BATCH, 512>>>(w1_t, b1_t, w2_t, b2_t, w1_c, b1_c, w2_c, b2_c);
    rem_kernel<<<BATCH*256, 256>>>(x_t, out);
    gemm_fused<<<3072, 256, SMEM_BYTES>>>(x_t, x_c, out);
}